// round 6
// baseline (speedup 1.0000x reference)
#include <cuda_runtime.h>
#include <cuda_bf16.h>
#include <cstdint>

// ---------------------------------------------------------------------------
// DigitConvolutionalModel via mma.sync bf16 split-precision (bf16x3) GEMMs.
// R6: conv with 2 samples/warp + depth-2 prefetch (MLP);
//     GEMM warp tile 32x64 (4 MMA per LDSM.x4, less smem traffic).
// ---------------------------------------------------------------------------

#define BATCH 65536
#define K1P   704

// ---- scratch (__device__ globals; no allocations allowed) ----
__device__ __nv_bfloat16 g_c_hi [BATCH * K1P];
__device__ __nv_bfloat16 g_c_lo [BATCH * K1P];
__device__ __nv_bfloat16 g_h1_hi[BATCH * 128];
__device__ __nv_bfloat16 g_h1_lo[BATCH * 128];
__device__ __nv_bfloat16 g_h2_hi[BATCH * 512];
__device__ __nv_bfloat16 g_h2_lo[BATCH * 512];
__device__ float         g_h3   [BATCH * 256];
__device__ __nv_bfloat16 g_w1_hi[128 * K1P];
__device__ __nv_bfloat16 g_w1_lo[128 * K1P];
__device__ __nv_bfloat16 g_w2_hi[512 * 128];
__device__ __nv_bfloat16 g_w2_lo[512 * 128];
__device__ __nv_bfloat16 g_w3_hi[256 * 512];
__device__ __nv_bfloat16 g_w3_lo[256 * 512];

// ---------------------------------------------------------------------------
// helpers
// ---------------------------------------------------------------------------
__device__ __forceinline__ uint32_t smem_u32(const void* p) {
    uint32_t a;
    asm("{ .reg .u64 t; cvta.to.shared.u64 t, %1; cvt.u32.u64 %0, t; }"
        : "=r"(a) : "l"(p));
    return a;
}
#define SWZ128(off) ((off) ^ (((off) >> 3) & 0x70))

#define CP_ASYNC16(saddr, gptr) \
    asm volatile("cp.async.cg.shared.global [%0], [%1], 16;" \
                 :: "r"(saddr), "l"(gptr) : "memory")
#define CP_COMMIT() asm volatile("cp.async.commit_group;" ::: "memory")
#define CP_WAIT0()  asm volatile("cp.async.wait_group 0;" ::: "memory")

#define LDSM_X4(r, addr) \
    asm volatile("ldmatrix.sync.aligned.m8n8.x4.shared.b16 {%0,%1,%2,%3}, [%4];" \
                 : "=r"((r)[0]), "=r"((r)[1]), "=r"((r)[2]), "=r"((r)[3]) \
                 : "r"(addr))

#define MMA_BF16(d, a, b0, b1) \
    asm volatile("mma.sync.aligned.m16n8k16.row.col.f32.bf16.bf16.f32 " \
                 "{%0,%1,%2,%3}, {%4,%5,%6,%7}, {%8,%9}, {%0,%1,%2,%3};" \
                 : "+f"((d)[0]), "+f"((d)[1]), "+f"((d)[2]), "+f"((d)[3]) \
                 : "r"((a)[0]), "r"((a)[1]), "r"((a)[2]), "r"((a)[3]), \
                   "r"(b0), "r"(b1))

__device__ __forceinline__ unsigned pack_bf2(__nv_bfloat16 a, __nv_bfloat16 b) {
    return (unsigned)__bfloat16_as_ushort(a) | ((unsigned)__bfloat16_as_ushort(b) << 16);
}

// ---------------------------------------------------------------------------
// Conv v3: 2 samples per warp (2 independent LDG chains), depth-2 row
// prefetch, shuffle taps, smem-staged uint4 output.
// ---------------------------------------------------------------------------
__global__ void __launch_bounds__(256)
conv_kernel(const float* __restrict__ x,
            const float* __restrict__ wc,
            __nv_bfloat16* __restrict__ chi,
            __nv_bfloat16* __restrict__ clo)
{
    __shared__ float wsh[9];
    __shared__ __align__(16) __nv_bfloat16 ohi[16][704];
    __shared__ __align__(16) __nv_bfloat16 olo[16][704];

    const int tid  = threadIdx.x;
    const int wid  = tid >> 5;
    const int lane = tid & 31;
    const int s0   = blockIdx.x * 16 + wid * 2;

    if (tid < 9) wsh[tid] = wc[tid];
    __syncthreads();

    const float w0 = wsh[0], w1 = wsh[1], w2 = wsh[2];
    const float w3 = wsh[3], w4 = wsh[4], w5 = wsh[5];
    const float w6 = wsh[6], w7 = wsh[7], w8 = wsh[8];

    const float* x0 = x + (size_t)s0 * 784;
    const float* x1 = x0 + 784;
    const bool ld = (lane < 28);

    // preload rows 0..3 of both samples (independent chains)
    float a0 = ld ? x0[lane]          : 0.f;
    float a1 = ld ? x1[lane]          : 0.f;
    float b0 = ld ? x0[28 + lane]     : 0.f;
    float b1 = ld ? x1[28 + lane]     : 0.f;
    float c0 = ld ? x0[56 + lane]     : 0.f;
    float c1 = ld ? x1[56 + lane]     : 0.f;
    float d0 = ld ? x0[84 + lane]     : 0.f;
    float d1 = ld ? x1[84 + lane]     : 0.f;

    #pragma unroll 1
    for (int oi = 0; oi < 26; ++oi) {
        // prefetch row oi+4 (2 iterations ahead of use)
        const bool pf = (oi < 24) && ld;
        float e0 = pf ? x0[(oi + 4) * 28 + lane] : 0.f;
        float e1 = pf ? x1[(oi + 4) * 28 + lane] : 0.f;

        float p1 = __shfl_down_sync(0xffffffffu, a0, 1);
        float p2 = __shfl_down_sync(0xffffffffu, a0, 2);
        float q1 = __shfl_down_sync(0xffffffffu, b0, 1);
        float q2 = __shfl_down_sync(0xffffffffu, b0, 2);
        float r1 = __shfl_down_sync(0xffffffffu, c0, 1);
        float r2 = __shfl_down_sync(0xffffffffu, c0, 2);
        float sum0 = a0 * w0;
        sum0 = fmaf(p1, w1, sum0); sum0 = fmaf(p2, w2, sum0);
        sum0 = fmaf(b0, w3, sum0); sum0 = fmaf(q1, w4, sum0);
        sum0 = fmaf(q2, w5, sum0); sum0 = fmaf(c0, w6, sum0);
        sum0 = fmaf(r1, w7, sum0); sum0 = fmaf(r2, w8, sum0);

        float u1 = __shfl_down_sync(0xffffffffu, a1, 1);
        float u2 = __shfl_down_sync(0xffffffffu, a1, 2);
        float v1 = __shfl_down_sync(0xffffffffu, b1, 1);
        float v2 = __shfl_down_sync(0xffffffffu, b1, 2);
        float t1 = __shfl_down_sync(0xffffffffu, c1, 1);
        float t2 = __shfl_down_sync(0xffffffffu, c1, 2);
        float sum1 = a1 * w0;
        sum1 = fmaf(u1, w1, sum1); sum1 = fmaf(u2, w2, sum1);
        sum1 = fmaf(b1, w3, sum1); sum1 = fmaf(v1, w4, sum1);
        sum1 = fmaf(v2, w5, sum1); sum1 = fmaf(c1, w6, sum1);
        sum1 = fmaf(t1, w7, sum1); sum1 = fmaf(t2, w8, sum1);

        if (lane < 26) {
            const int o = oi * 26 + lane;
            __nv_bfloat16 h0 = __float2bfloat16(sum0);
            ohi[wid * 2 + 0][o] = h0;
            olo[wid * 2 + 0][o] = __float2bfloat16(sum0 - __bfloat162float(h0));
            __nv_bfloat16 h1 = __float2bfloat16(sum1);
            ohi[wid * 2 + 1][o] = h1;
            olo[wid * 2 + 1][o] = __float2bfloat16(sum1 - __bfloat162float(h1));
        }
        a0 = b0; b0 = c0; c0 = d0; d0 = e0;
        a1 = b1; b1 = c1; c1 = d1; d1 = e1;
    }
    // zero pad 676..703
    if (lane < 28) {
        ohi[wid * 2 + 0][676 + lane] = __float2bfloat16(0.f);
        olo[wid * 2 + 0][676 + lane] = __float2bfloat16(0.f);
        ohi[wid * 2 + 1][676 + lane] = __float2bfloat16(0.f);
        olo[wid * 2 + 1][676 + lane] = __float2bfloat16(0.f);
    }
    __syncwarp();

    #pragma unroll
    for (int sl = 0; sl < 2; ++sl) {
        const size_t base = (size_t)(s0 + sl) * K1P;
        uint4* gh = (uint4*)(chi + base);
        uint4* gl = (uint4*)(clo + base);
        const uint4* sh = (const uint4*)ohi[wid * 2 + sl];
        const uint4* slp = (const uint4*)olo[wid * 2 + sl];
        #pragma unroll
        for (int i = lane; i < 88; i += 32) {
            gh[i] = sh[i];
            gl[i] = slp[i];
        }
    }
}

// ---------------------------------------------------------------------------
// Weight split: fp32 [N,Ks] -> bf16 hi/lo [N,Kd] zero-padded.
// ---------------------------------------------------------------------------
__global__ void wconv_kernel(const float* __restrict__ src, int N, int Ks, int Kd,
                             __nv_bfloat16* __restrict__ hi,
                             __nv_bfloat16* __restrict__ lo)
{
    int i = blockIdx.x * blockDim.x + threadIdx.x;
    if (i >= N * Kd) return;
    int n = i / Kd, k = i - n * Kd;
    float v = (k < Ks) ? src[(size_t)n * Ks + k] : 0.f;
    __nv_bfloat16 h = __float2bfloat16(v);
    hi[i] = h;
    lo[i] = __float2bfloat16(v - __bfloat162float(h));
}

// ---------------------------------------------------------------------------
// mma.sync split-bf16 GEMM: C[m,n] = act( sum_k A[m,k]*W[n,k] + bias[n] )
// CTA: 64x128 tile, 4 warps (32x64 each), 128 threads, BK=64,
// double-buffered cp.async, ~97KB smem -> 2 CTAs/SM.
// Requires: M%64==0, N%128==0, K%64==0.
// ---------------------------------------------------------------------------
#define SM_A_HI 0
#define SM_A_LO 8192
#define SM_B_HI 16384
#define SM_B_LO 32768
#define BUF_STRIDE 49152
#define SM_BIAS (2 * BUF_STRIDE)
#define SMEM_SZ (SM_BIAS + 512)

template <bool RELU, bool SPLIT>
__global__ void __launch_bounds__(128, 2)
gemm_mma(const __nv_bfloat16* __restrict__ Ah, const __nv_bfloat16* __restrict__ Al,
         const __nv_bfloat16* __restrict__ Bh, const __nv_bfloat16* __restrict__ Bl,
         const float* __restrict__ bias,
         void* __restrict__ outHi, void* __restrict__ outLo,
         int N, int K)
{
    extern __shared__ __align__(1024) char smem[];
    const uint32_t sb = smem_u32(smem);
    const int tid  = threadIdx.x;
    const int wid  = tid >> 5;
    const int lane = tid & 31;
    const int m0   = blockIdx.y * 64;
    const int n0   = blockIdx.x * 128;
    float* bs = (float*)(smem + SM_BIAS);

    bs[tid] = bias[n0 + tid];

    // ---- loader addressing (128B rows, SW128) ----
    uint32_t soA[4]; size_t gaOff[4];
    #pragma unroll
    for (int i = 0; i < 4; ++i) {
        const int idx = tid + 128 * i;
        const int row = idx >> 3, ch = idx & 7;
        soA[i]  = SWZ128((uint32_t)row * 128 + ch * 16);
        gaOff[i] = (size_t)(m0 + row) * K + ch * 8;
    }
    uint32_t soB[8]; size_t gbOff[8];
    #pragma unroll
    for (int i = 0; i < 8; ++i) {
        const int idx = tid + 128 * i;
        const int row = idx >> 3, ch = idx & 7;
        soB[i]  = SWZ128((uint32_t)row * 128 + ch * 16);
        gbOff[i] = (size_t)(n0 + row) * K + ch * 8;
    }

    // prefetch tile 0 into buffer 0
    #pragma unroll
    for (int i = 0; i < 4; ++i) {
        CP_ASYNC16(sb + SM_A_HI + soA[i], Ah + gaOff[i]);
        CP_ASYNC16(sb + SM_A_LO + soA[i], Al + gaOff[i]);
    }
    #pragma unroll
    for (int i = 0; i < 8; ++i) {
        CP_ASYNC16(sb + SM_B_HI + soB[i], Bh + gbOff[i]);
        CP_ASYNC16(sb + SM_B_LO + soB[i], Bl + gbOff[i]);
    }
    CP_COMMIT();

    // ---- warp tiling: wm in {0,1} (32 rows), wn in {0,1} (64 cols) ----
    const int wm = wid & 1;
    const int wn = wid >> 1;
    const int lrow  = lane & 15;
    const int lhalf = (lane >> 4) * 16;

    float acc[2][8][4];
    #pragma unroll
    for (int mi = 0; mi < 2; ++mi)
        #pragma unroll
        for (int nj = 0; nj < 8; ++nj)
            #pragma unroll
            for (int q = 0; q < 4; ++q) acc[mi][nj][q] = 0.f;

    int buf = 0;
    for (int kt = 0; kt < K; kt += 64) {
        CP_WAIT0();
        __syncthreads();

        if (kt + 64 < K) {
            const uint32_t nb = sb + (buf ^ 1) * BUF_STRIDE;
            #pragma unroll
            for (int i = 0; i < 4; ++i) {
                CP_ASYNC16(nb + SM_A_HI + soA[i], Ah + gaOff[i] + kt + 64);
                CP_ASYNC16(nb + SM_A_LO + soA[i], Al + gaOff[i] + kt + 64);
            }
            #pragma unroll
            for (int i = 0; i < 8; ++i) {
                CP_ASYNC16(nb + SM_B_HI + soB[i], Bh + gbOff[i] + kt + 64);
                CP_ASYNC16(nb + SM_B_LO + soB[i], Bl + gbOff[i] + kt + 64);
            }
            CP_COMMIT();
        }

        const uint32_t cb = sb + buf * BUF_STRIDE;
        #pragma unroll
        for (int ks = 0; ks < 4; ++ks) {
            const uint32_t kbyte = ks * 32 + lhalf;
            uint32_t ah[2][4], al[2][4];
            #pragma unroll
            for (int mi = 0; mi < 2; ++mi) {
                const uint32_t row = wm * 32 + mi * 16 + lrow;
                const uint32_t off = SWZ128(row * 128 + kbyte);
                LDSM_X4(ah[mi], cb + SM_A_HI + off);
                LDSM_X4(al[mi], cb + SM_A_LO + off);
            }
            uint32_t bh[4][4], bl[4][4];
            #pragma unroll
            for (int g = 0; g < 4; ++g) {
                const uint32_t row = wn * 64 + g * 16 + lrow;
                const uint32_t off = SWZ128(row * 128 + kbyte);
                LDSM_X4(bh[g], cb + SM_B_HI + off);
                LDSM_X4(bl[g], cb + SM_B_LO + off);
            }
            #pragma unroll
            for (int mi = 0; mi < 2; ++mi) {
                #pragma unroll
                for (int nj = 0; nj < 8; ++nj) {
                    const int g = nj >> 1, h = nj & 1;
                    MMA_BF16(acc[mi][nj], ah[mi], bh[g][h], bh[g][h + 2]);
                    MMA_BF16(acc[mi][nj], al[mi], bh[g][h], bh[g][h + 2]);
                    MMA_BF16(acc[mi][nj], ah[mi], bl[g][h], bl[g][h + 2]);
                }
            }
        }
        __syncthreads();
        buf ^= 1;
    }

    // ---- epilogue: bias (+relu), direct global stores ----
    const int qr = lane >> 2;
    const int qc = (lane & 3) * 2;
    #pragma unroll
    for (int mi = 0; mi < 2; ++mi) {
        #pragma unroll
        for (int nj = 0; nj < 8; ++nj) {
            const int col = wn * 64 + nj * 8 + qc;
            const float b0 = bs[col], b1 = bs[col + 1];
            #pragma unroll
            for (int half = 0; half < 2; ++half) {
                const int row = wm * 32 + mi * 16 + qr + half * 8;
                float v0 = acc[mi][nj][half * 2 + 0] + b0;
                float v1 = acc[mi][nj][half * 2 + 1] + b1;
                if (RELU) { v0 = fmaxf(v0, 0.f); v1 = fmaxf(v1, 0.f); }
                const size_t g = (size_t)(m0 + row) * N + n0 + col;
                if (SPLIT) {
                    __nv_bfloat16 h0 = __float2bfloat16(v0);
                    __nv_bfloat16 h1 = __float2bfloat16(v1);
                    *(uint32_t*)((__nv_bfloat16*)outHi + g) = pack_bf2(h0, h1);
                    __nv_bfloat16 l0 = __float2bfloat16(v0 - __bfloat162float(h0));
                    __nv_bfloat16 l1 = __float2bfloat16(v1 - __bfloat162float(h1));
                    *(uint32_t*)((__nv_bfloat16*)outLo + g) = pack_bf2(l0, l1);
                } else {
                    *(float2*)((float*)outHi + g) = make_float2(v0, v1);
                }
            }
        }
    }
}

// ---------------------------------------------------------------------------
// Head: out[m,0..9] = h3[m,:] @ w4^T + b4 (K=256, N=10). fp32 input.
// ---------------------------------------------------------------------------
__global__ void __launch_bounds__(256)
head_kernel(const float* __restrict__ h3,
            const float* __restrict__ w4,
            const float* __restrict__ b4,
            float* __restrict__ out)
{
    __shared__ float ws[10 * 256];
    __shared__ float bsh[10];
    const int tid = threadIdx.x;
    #pragma unroll
    for (int i = tid; i < 2560; i += 256) ws[i] = w4[i];
    if (tid < 10) bsh[tid] = b4[tid];
    __syncthreads();

    const int warp = tid >> 5;
    const int lane = tid & 31;
    const int row  = blockIdx.x * 8 + warp;

    float acc[10];
    #pragma unroll
    for (int j = 0; j < 10; ++j) acc[j] = 0.f;

    const float* hr = h3 + (size_t)row * 256;
    #pragma unroll
    for (int t = 0; t < 8; ++t) {
        float xv = hr[t * 32 + lane];
        #pragma unroll
        for (int j = 0; j < 10; ++j)
            acc[j] = fmaf(xv, ws[j * 256 + t * 32 + lane], acc[j]);
    }
    #pragma unroll
    for (int j = 0; j < 10; ++j) {
        #pragma unroll
        for (int off = 16; off > 0; off >>= 1)
            acc[j] += __shfl_xor_sync(0xffffffffu, acc[j], off);
    }
    if (lane == 0) {
        #pragma unroll
        for (int j = 0; j < 10; ++j)
            out[(size_t)row * 10 + j] = acc[j] + bsh[j];
    }
}

// ---------------------------------------------------------------------------
// Launch
// ---------------------------------------------------------------------------
extern "C" void kernel_launch(void* const* d_in, const int* in_sizes, int n_in,
                              void* d_out, int out_size)
{
    const float* x  = (const float*)d_in[0];
    const float* wc = (const float*)d_in[1];
    const float* w1 = (const float*)d_in[2];
    const float* b1 = (const float*)d_in[3];
    const float* w2 = (const float*)d_in[4];
    const float* b2 = (const float*)d_in[5];
    const float* w3 = (const float*)d_in[6];
    const float* b3 = (const float*)d_in[7];
    const float* w4 = (const float*)d_in[8];
    const float* b4 = (const float*)d_in[9];
    float* out = (float*)d_out;

    __nv_bfloat16 *chi, *clo, *h1h, *h1l, *h2h, *h2l;
    __nv_bfloat16 *w1h, *w1l, *w2h, *w2l, *w3h, *w3l;
    float* h3;
    cudaGetSymbolAddress((void**)&chi, g_c_hi);
    cudaGetSymbolAddress((void**)&clo, g_c_lo);
    cudaGetSymbolAddress((void**)&h1h, g_h1_hi);
    cudaGetSymbolAddress((void**)&h1l, g_h1_lo);
    cudaGetSymbolAddress((void**)&h2h, g_h2_hi);
    cudaGetSymbolAddress((void**)&h2l, g_h2_lo);
    cudaGetSymbolAddress((void**)&h3,  g_h3);
    cudaGetSymbolAddress((void**)&w1h, g_w1_hi);
    cudaGetSymbolAddress((void**)&w1l, g_w1_lo);
    cudaGetSymbolAddress((void**)&w2h, g_w2_hi);
    cudaGetSymbolAddress((void**)&w2l, g_w2_lo);
    cudaGetSymbolAddress((void**)&w3h, g_w3_hi);
    cudaGetSymbolAddress((void**)&w3l, g_w3_lo);

    cudaFuncSetAttribute(gemm_mma<true, true>,
                         cudaFuncAttributeMaxDynamicSharedMemorySize, SMEM_SZ);
    cudaFuncSetAttribute(gemm_mma<true, false>,
                         cudaFuncAttributeMaxDynamicSharedMemorySize, SMEM_SZ);

    wconv_kernel<<<(128 * K1P + 255) / 256, 256>>>(w1, 128, 676, K1P, w1h, w1l);
    wconv_kernel<<<(512 * 128 + 255) / 256, 256>>>(w2, 512, 128, 128, w2h, w2l);
    wconv_kernel<<<(256 * 512 + 255) / 256, 256>>>(w3, 256, 512, 512, w3h, w3l);

    conv_kernel<<<BATCH / 16, 256>>>(x, wc, chi, clo);

    // L1: [B,704] x [128,704]^T -> relu -> h1 (split)
    gemm_mma<true, true><<<dim3(1, BATCH / 64), 128, SMEM_SZ>>>(
        chi, clo, w1h, w1l, b1, h1h, h1l, 128, K1P);
    // L2: [B,128] x [512,128]^T -> relu -> h2 (split)
    gemm_mma<true, true><<<dim3(4, BATCH / 64), 128, SMEM_SZ>>>(
        h1h, h1l, w2h, w2l, b2, h2h, h2l, 512, 128);
    // L3: [B,512] x [256,512]^T -> relu -> h3 (fp32)
    gemm_mma<true, false><<<dim3(2, BATCH / 64), 128, SMEM_SZ>>>(
        h2h, h2l, w3h, w3l, b3, h3, nullptr, 256, 512);
    // L4
    head_kernel<<<BATCH / 8, 256>>>(h3, w4, b4, out);
}

// round 7
// speedup vs baseline: 1.3165x; 1.3165x over previous
#include <cuda_runtime.h>
#include <cuda_fp16.h>
#include <cstdint>

// ---------------------------------------------------------------------------
// DigitConvolutionalModel via mma.sync fp16 GEMMs, weight-only hi/lo split.
// Activations: single fp16 (2^-12 rounding). Weights: fp16 hi + fp16 lo
// (exact to ~2^-19). 2 MMAs per fragment: A*Wh + A*Wl.
// x[65536,784] -> conv3x3 -> 676(pad 704) -> fc 128 -> fc 512 -> fc 256 -> fc 10
// ---------------------------------------------------------------------------

#define BATCH 65536
#define K1P   704

// ---- scratch (__device__ globals; no allocations allowed) ----
__device__ __half g_c [BATCH * K1P];
__device__ __half g_h1[BATCH * 128];
__device__ __half g_h2[BATCH * 512];
__device__ float  g_h3[BATCH * 256];
__device__ __half g_w1_hi[128 * K1P];
__device__ __half g_w1_lo[128 * K1P];
__device__ __half g_w2_hi[512 * 128];
__device__ __half g_w2_lo[512 * 128];
__device__ __half g_w3_hi[256 * 512];
__device__ __half g_w3_lo[256 * 512];

// ---------------------------------------------------------------------------
// helpers
// ---------------------------------------------------------------------------
__device__ __forceinline__ uint32_t smem_u32(const void* p) {
    uint32_t a;
    asm("{ .reg .u64 t; cvta.to.shared.u64 t, %1; cvt.u32.u64 %0, t; }"
        : "=r"(a) : "l"(p));
    return a;
}
#define SWZ128(off) ((off) ^ (((off) >> 3) & 0x70))

#define CP_ASYNC16(saddr, gptr) \
    asm volatile("cp.async.cg.shared.global [%0], [%1], 16;" \
                 :: "r"(saddr), "l"(gptr) : "memory")
#define CP_COMMIT() asm volatile("cp.async.commit_group;" ::: "memory")
#define CP_WAIT0()  asm volatile("cp.async.wait_group 0;" ::: "memory")

#define LDSM_X4(r, addr) \
    asm volatile("ldmatrix.sync.aligned.m8n8.x4.shared.b16 {%0,%1,%2,%3}, [%4];" \
                 : "=r"((r)[0]), "=r"((r)[1]), "=r"((r)[2]), "=r"((r)[3]) \
                 : "r"(addr))

#define MMA_F16(d, a, b0, b1) \
    asm volatile("mma.sync.aligned.m16n8k16.row.col.f32.f16.f16.f32 " \
                 "{%0,%1,%2,%3}, {%4,%5,%6,%7}, {%8,%9}, {%0,%1,%2,%3};" \
                 : "+f"((d)[0]), "+f"((d)[1]), "+f"((d)[2]), "+f"((d)[3]) \
                 : "r"((a)[0]), "r"((a)[1]), "r"((a)[2]), "r"((a)[3]), \
                   "r"(b0), "r"(b1))

__device__ __forceinline__ unsigned pack_h2(__half a, __half b) {
    return (unsigned)__half_as_ushort(a) | ((unsigned)__half_as_ushort(b) << 16);
}

// ---------------------------------------------------------------------------
// Conv: one warp per sample. Rolling 3-row register window; shuffle taps;
// single fp16 output, smem-staged, uint4 copy out. K padded to 704.
// ---------------------------------------------------------------------------
__global__ void __launch_bounds__(256)
conv_kernel(const float* __restrict__ x,
            const float* __restrict__ wc,
            __half* __restrict__ cout)
{
    __shared__ float wsh[9];
    __shared__ __align__(16) __half oh[8][704];

    const int tid  = threadIdx.x;
    const int wid  = tid >> 5;
    const int lane = tid & 31;
    const int s    = blockIdx.x * 8 + wid;

    if (tid < 9) wsh[tid] = wc[tid];
    __syncthreads();

    const float w0 = wsh[0], w1 = wsh[1], w2 = wsh[2];
    const float w3 = wsh[3], w4 = wsh[4], w5 = wsh[5];
    const float w6 = wsh[6], w7 = wsh[7], w8 = wsh[8];

    const float* xr = x + (size_t)s * 784;
    float a = (lane < 28) ? xr[lane]      : 0.f;
    float b = (lane < 28) ? xr[28 + lane] : 0.f;

    #pragma unroll 1
    for (int oi = 0; oi < 26; ++oi) {
        float c = (lane < 28) ? xr[(oi + 2) * 28 + lane] : 0.f;
        float a1 = __shfl_down_sync(0xffffffffu, a, 1);
        float a2 = __shfl_down_sync(0xffffffffu, a, 2);
        float b1 = __shfl_down_sync(0xffffffffu, b, 1);
        float b2 = __shfl_down_sync(0xffffffffu, b, 2);
        float c1 = __shfl_down_sync(0xffffffffu, c, 1);
        float c2 = __shfl_down_sync(0xffffffffu, c, 2);
        float sum = a * w0; sum = fmaf(a1, w1, sum); sum = fmaf(a2, w2, sum);
        sum = fmaf(b, w3, sum); sum = fmaf(b1, w4, sum); sum = fmaf(b2, w5, sum);
        sum = fmaf(c, w6, sum); sum = fmaf(c1, w7, sum); sum = fmaf(c2, w8, sum);
        if (lane < 26)
            oh[wid][oi * 26 + lane] = __float2half_rn(sum);
        a = b; b = c;
    }
    if (lane < 28)
        oh[wid][676 + lane] = __ushort_as_half((unsigned short)0);
    __syncwarp();

    uint4* g = (uint4*)(cout + (size_t)s * K1P);
    const uint4* sh = (const uint4*)oh[wid];
    #pragma unroll
    for (int i = lane; i < 88; i += 32)
        g[i] = sh[i];
}

// ---------------------------------------------------------------------------
// Weight split: fp32 [N,Ks] -> fp16 hi/lo [N,Kd] zero-padded.
// ---------------------------------------------------------------------------
__global__ void wconv_kernel(const float* __restrict__ src, int N, int Ks, int Kd,
                             __half* __restrict__ hi,
                             __half* __restrict__ lo)
{
    int i = blockIdx.x * blockDim.x + threadIdx.x;
    if (i >= N * Kd) return;
    int n = i / Kd, k = i - n * Kd;
    float v = (k < Ks) ? src[(size_t)n * Ks + k] : 0.f;
    __half h = __float2half_rn(v);
    hi[i] = h;
    lo[i] = __float2half_rn(v - __half2float(h));
}

// ---------------------------------------------------------------------------
// mma.sync fp16 GEMM, weight-split: C[m,n] = act( sum_k A[m,k]*W[n,k] + b[n] )
// A: single fp16 [M,K]; W: fp16 hi/lo [N,K]. 2 MMAs per fragment pair.
// CTA: 64x128 tile, 4 warps (32x64 each), 128 threads, BK=64,
// double-buffered cp.async (~81KB smem -> 2 CTAs/SM).
// HALF_OUT=true: fp16 out; else fp32 out. M%64==0, N%128==0, K%64==0.
// ---------------------------------------------------------------------------
#define SM_A    0
#define SM_B_HI 8192
#define SM_B_LO 24576
#define BUF_STRIDE 40960
#define SM_BIAS (2 * BUF_STRIDE)
#define SMEM_SZ (SM_BIAS + 512)

template <bool RELU, bool HALF_OUT>
__global__ void __launch_bounds__(128, 2)
gemm_mma(const __half* __restrict__ A,
         const __half* __restrict__ Bh, const __half* __restrict__ Bl,
         const float* __restrict__ bias,
         void* __restrict__ outp,
         int N, int K)
{
    extern __shared__ __align__(1024) char smem[];
    const uint32_t sb = smem_u32(smem);
    const int tid  = threadIdx.x;
    const int wid  = tid >> 5;
    const int lane = tid & 31;
    const int m0   = blockIdx.y * 64;
    const int n0   = blockIdx.x * 128;
    float* bs = (float*)(smem + SM_BIAS);

    bs[tid] = bias[n0 + tid];

    // ---- loader addressing (128B rows, SW128) ----
    uint32_t soA[4]; size_t gaOff[4];
    #pragma unroll
    for (int i = 0; i < 4; ++i) {
        const int idx = tid + 128 * i;
        const int row = idx >> 3, ch = idx & 7;
        soA[i]  = SWZ128((uint32_t)row * 128 + ch * 16);
        gaOff[i] = (size_t)(m0 + row) * K + ch * 8;
    }
    uint32_t soB[8]; size_t gbOff[8];
    #pragma unroll
    for (int i = 0; i < 8; ++i) {
        const int idx = tid + 128 * i;
        const int row = idx >> 3, ch = idx & 7;
        soB[i]  = SWZ128((uint32_t)row * 128 + ch * 16);
        gbOff[i] = (size_t)(n0 + row) * K + ch * 8;
    }

    // prefetch tile 0 into buffer 0
    #pragma unroll
    for (int i = 0; i < 4; ++i)
        CP_ASYNC16(sb + SM_A + soA[i], A + gaOff[i]);
    #pragma unroll
    for (int i = 0; i < 8; ++i) {
        CP_ASYNC16(sb + SM_B_HI + soB[i], Bh + gbOff[i]);
        CP_ASYNC16(sb + SM_B_LO + soB[i], Bl + gbOff[i]);
    }
    CP_COMMIT();

    // ---- warp tiling: wm in {0,1} (32 rows), wn in {0,1} (64 cols) ----
    const int wm = wid & 1;
    const int wn = wid >> 1;
    const int lrow  = lane & 15;
    const int lhalf = (lane >> 4) * 16;

    float acc[2][8][4];
    #pragma unroll
    for (int mi = 0; mi < 2; ++mi)
        #pragma unroll
        for (int nj = 0; nj < 8; ++nj)
            #pragma unroll
            for (int q = 0; q < 4; ++q) acc[mi][nj][q] = 0.f;

    int buf = 0;
    for (int kt = 0; kt < K; kt += 64) {
        CP_WAIT0();
        __syncthreads();

        if (kt + 64 < K) {
            const uint32_t nb = sb + (buf ^ 1) * BUF_STRIDE;
            #pragma unroll
            for (int i = 0; i < 4; ++i)
                CP_ASYNC16(nb + SM_A + soA[i], A + gaOff[i] + kt + 64);
            #pragma unroll
            for (int i = 0; i < 8; ++i) {
                CP_ASYNC16(nb + SM_B_HI + soB[i], Bh + gbOff[i] + kt + 64);
                CP_ASYNC16(nb + SM_B_LO + soB[i], Bl + gbOff[i] + kt + 64);
            }
            CP_COMMIT();
        }

        const uint32_t cb = sb + buf * BUF_STRIDE;
        #pragma unroll
        for (int ks = 0; ks < 4; ++ks) {
            const uint32_t kbyte = ks * 32 + lhalf;
            uint32_t av[2][4];
            #pragma unroll
            for (int mi = 0; mi < 2; ++mi) {
                const uint32_t row = wm * 32 + mi * 16 + lrow;
                const uint32_t off = SWZ128(row * 128 + kbyte);
                LDSM_X4(av[mi], cb + SM_A + off);
            }
            uint32_t bh[4][4], bl[4][4];
            #pragma unroll
            for (int g = 0; g < 4; ++g) {
                const uint32_t row = wn * 64 + g * 16 + lrow;
                const uint32_t off = SWZ128(row * 128 + kbyte);
                LDSM_X4(bh[g], cb + SM_B_HI + off);
                LDSM_X4(bl[g], cb + SM_B_LO + off);
            }
            #pragma unroll
            for (int mi = 0; mi < 2; ++mi) {
                #pragma unroll
                for (int nj = 0; nj < 8; ++nj) {
                    const int g = nj >> 1, h = nj & 1;
                    MMA_F16(acc[mi][nj], av[mi], bh[g][h], bh[g][h + 2]);
                    MMA_F16(acc[mi][nj], av[mi], bl[g][h], bl[g][h + 2]);
                }
            }
        }
        __syncthreads();
        buf ^= 1;
    }

    // ---- epilogue: bias (+relu), direct global stores ----
    const int qr = lane >> 2;
    const int qc = (lane & 3) * 2;
    #pragma unroll
    for (int mi = 0; mi < 2; ++mi) {
        #pragma unroll
        for (int nj = 0; nj < 8; ++nj) {
            const int col = wn * 64 + nj * 8 + qc;
            const float b0 = bs[col], b1 = bs[col + 1];
            #pragma unroll
            for (int half = 0; half < 2; ++half) {
                const int row = wm * 32 + mi * 16 + qr + half * 8;
                float v0 = acc[mi][nj][half * 2 + 0] + b0;
                float v1 = acc[mi][nj][half * 2 + 1] + b1;
                if (RELU) { v0 = fmaxf(v0, 0.f); v1 = fmaxf(v1, 0.f); }
                const size_t g = (size_t)(m0 + row) * N + n0 + col;
                if (HALF_OUT) {
                    *(uint32_t*)((__half*)outp + g) =
                        pack_h2(__float2half_rn(v0), __float2half_rn(v1));
                } else {
                    *(float2*)((float*)outp + g) = make_float2(v0, v1);
                }
            }
        }
    }
}

// ---------------------------------------------------------------------------
// Head: out[m,0..9] = h3[m,:] @ w4^T + b4 (K=256, N=10). fp32 input.
// ---------------------------------------------------------------------------
__global__ void __launch_bounds__(256)
head_kernel(const float* __restrict__ h3,
            const float* __restrict__ w4,
            const float* __restrict__ b4,
            float* __restrict__ out)
{
    __shared__ float ws[10 * 256];
    __shared__ float bsh[10];
    const int tid = threadIdx.x;
    #pragma unroll
    for (int i = tid; i < 2560; i += 256) ws[i] = w4[i];
    if (tid < 10) bsh[tid] = b4[tid];
    __syncthreads();

    const int warp = tid >> 5;
    const int lane = tid & 31;
    const int row  = blockIdx.x * 8 + warp;

    float acc[10];
    #pragma unroll
    for (int j = 0; j < 10; ++j) acc[j] = 0.f;

    const float* hr = h3 + (size_t)row * 256;
    #pragma unroll
    for (int t = 0; t < 8; ++t) {
        float xv = hr[t * 32 + lane];
        #pragma unroll
        for (int j = 0; j < 10; ++j)
            acc[j] = fmaf(xv, ws[j * 256 + t * 32 + lane], acc[j]);
    }
    #pragma unroll
    for (int j = 0; j < 10; ++j) {
        #pragma unroll
        for (int off = 16; off > 0; off >>= 1)
            acc[j] += __shfl_xor_sync(0xffffffffu, acc[j], off);
    }
    if (lane == 0) {
        #pragma unroll
        for (int j = 0; j < 10; ++j)
            out[(size_t)row * 10 + j] = acc[j] + bsh[j];
    }
}

// ---------------------------------------------------------------------------
// Launch
// ---------------------------------------------------------------------------
extern "C" void kernel_launch(void* const* d_in, const int* in_sizes, int n_in,
                              void* d_out, int out_size)
{
    const float* x  = (const float*)d_in[0];
    const float* wc = (const float*)d_in[1];
    const float* w1 = (const float*)d_in[2];
    const float* b1 = (const float*)d_in[3];
    const float* w2 = (const float*)d_in[4];
    const float* b2 = (const float*)d_in[5];
    const float* w3 = (const float*)d_in[6];
    const float* b3 = (const float*)d_in[7];
    const float* w4 = (const float*)d_in[8];
    const float* b4 = (const float*)d_in[9];
    float* out = (float*)d_out;

    __half *c, *h1, *h2;
    __half *w1h, *w1l, *w2h, *w2l, *w3h, *w3l;
    float* h3;
    cudaGetSymbolAddress((void**)&c,   g_c);
    cudaGetSymbolAddress((void**)&h1,  g_h1);
    cudaGetSymbolAddress((void**)&h2,  g_h2);
    cudaGetSymbolAddress((void**)&h3,  g_h3);
    cudaGetSymbolAddress((void**)&w1h, g_w1_hi);
    cudaGetSymbolAddress((void**)&w1l, g_w1_lo);
    cudaGetSymbolAddress((void**)&w2h, g_w2_hi);
    cudaGetSymbolAddress((void**)&w2l, g_w2_lo);
    cudaGetSymbolAddress((void**)&w3h, g_w3_hi);
    cudaGetSymbolAddress((void**)&w3l, g_w3_lo);

    cudaFuncSetAttribute(gemm_mma<true, true>,
                         cudaFuncAttributeMaxDynamicSharedMemorySize, SMEM_SZ);
    cudaFuncSetAttribute(gemm_mma<true, false>,
                         cudaFuncAttributeMaxDynamicSharedMemorySize, SMEM_SZ);

    wconv_kernel<<<(128 * K1P + 255) / 256, 256>>>(w1, 128, 676, K1P, w1h, w1l);
    wconv_kernel<<<(512 * 128 + 255) / 256, 256>>>(w2, 512, 128, 128, w2h, w2l);
    wconv_kernel<<<(256 * 512 + 255) / 256, 256>>>(w3, 256, 512, 512, w3h, w3l);

    conv_kernel<<<BATCH / 8, 256>>>(x, wc, c);

    // L1: [B,704] x [128,704]^T -> relu -> h1 (fp16)
    gemm_mma<true, true><<<dim3(1, BATCH / 64), 128, SMEM_SZ>>>(
        c, w1h, w1l, b1, h1, 128, K1P);
    // L2: [B,128] x [512,128]^T -> relu -> h2 (fp16)
    gemm_mma<true, true><<<dim3(4, BATCH / 64), 128, SMEM_SZ>>>(
        h1, w2h, w2l, b2, h2, 512, 128);
    // L3: [B,512] x [256,512]^T -> relu -> h3 (fp32)
    gemm_mma<true, false><<<dim3(2, BATCH / 64), 128, SMEM_SZ>>>(
        h2, w3h, w3l, b3, h3, 256, 512);
    // L4
    head_kernel<<<BATCH / 8, 256>>>(h3, w4, b4, out);
}

// round 8
// speedup vs baseline: 1.4631x; 1.1113x over previous
#include <cuda_runtime.h>
#include <cuda_fp16.h>
#include <cstdint>

// ---------------------------------------------------------------------------
// DigitConvolutionalModel via mma.sync fp16 GEMMs, weight-only hi/lo split.
// R8: conv v4 (coalesced uint4 stage-in, 4 outputs per group via LDS.128);
//     h3 stored fp16 (halves L3-out + head-in traffic).
// ---------------------------------------------------------------------------

#define BATCH 65536
#define K1P   704

// ---- scratch (__device__ globals; no allocations allowed) ----
__device__ __half g_c [BATCH * K1P];
__device__ __half g_h1[BATCH * 128];
__device__ __half g_h2[BATCH * 512];
__device__ __half g_h3[BATCH * 256];
__device__ __half g_w1_hi[128 * K1P];
__device__ __half g_w1_lo[128 * K1P];
__device__ __half g_w2_hi[512 * 128];
__device__ __half g_w2_lo[512 * 128];
__device__ __half g_w3_hi[256 * 512];
__device__ __half g_w3_lo[256 * 512];

// ---------------------------------------------------------------------------
// helpers
// ---------------------------------------------------------------------------
__device__ __forceinline__ uint32_t smem_u32(const void* p) {
    uint32_t a;
    asm("{ .reg .u64 t; cvta.to.shared.u64 t, %1; cvt.u32.u64 %0, t; }"
        : "=r"(a) : "l"(p));
    return a;
}
#define SWZ128(off) ((off) ^ (((off) >> 3) & 0x70))

#define CP_ASYNC16(saddr, gptr) \
    asm volatile("cp.async.cg.shared.global [%0], [%1], 16;" \
                 :: "r"(saddr), "l"(gptr) : "memory")
#define CP_COMMIT() asm volatile("cp.async.commit_group;" ::: "memory")
#define CP_WAIT0()  asm volatile("cp.async.wait_group 0;" ::: "memory")

#define LDSM_X4(r, addr) \
    asm volatile("ldmatrix.sync.aligned.m8n8.x4.shared.b16 {%0,%1,%2,%3}, [%4];" \
                 : "=r"((r)[0]), "=r"((r)[1]), "=r"((r)[2]), "=r"((r)[3]) \
                 : "r"(addr))

#define MMA_F16(d, a, b0, b1) \
    asm volatile("mma.sync.aligned.m16n8k16.row.col.f32.f16.f16.f32 " \
                 "{%0,%1,%2,%3}, {%4,%5,%6,%7}, {%8,%9}, {%0,%1,%2,%3};" \
                 : "+f"((d)[0]), "+f"((d)[1]), "+f"((d)[2]), "+f"((d)[3]) \
                 : "r"((a)[0]), "r"((a)[1]), "r"((a)[2]), "r"((a)[3]), \
                   "r"(b0), "r"(b1))

__device__ __forceinline__ unsigned pack_h2(__half a, __half b) {
    return (unsigned)__half_as_ushort(a) | ((unsigned)__half_as_ushort(b) << 16);
}

// ---------------------------------------------------------------------------
// Conv v4: 16 samples/CTA. Coalesced uint4 gmem->smem stage, then each
// work-item computes 4 outputs in a row from 6 LDS.128 (3 rows x 2 float4).
// fp16 output staged in smem, uint4 copy out. K padded to 704.
// ---------------------------------------------------------------------------
#define CSAMP 16
#define CONV_XS_FLOATS (CSAMP * 784 + 4)          // +4-float pad for g=6 tail read
#define CONV_SMEM (CONV_XS_FLOATS * 4 + CSAMP * 704 * 2)

__global__ void __launch_bounds__(256)
conv_kernel(const float* __restrict__ x,
            const float* __restrict__ wc,
            __half* __restrict__ cout)
{
    extern __shared__ __align__(16) char csm[];
    float*  xs = (float*)csm;
    __half* oh = (__half*)(csm + CONV_XS_FLOATS * 4);
    __shared__ float wsh[9];

    const int tid = threadIdx.x;
    if (tid < 9) wsh[tid] = wc[tid];

    // stage 1: coalesced load 16*784 floats as uint4
    {
        const uint4* gx = (const uint4*)(x + (size_t)blockIdx.x * CSAMP * 784);
        uint4* sx = (uint4*)xs;
        #pragma unroll
        for (int i = tid; i < CSAMP * 196; i += 256)
            sx[i] = gx[i];
    }
    __syncthreads();

    const float w0 = wsh[0], w1 = wsh[1], w2 = wsh[2];
    const float w3 = wsh[3], w4 = wsh[4], w5 = wsh[5];
    const float w6 = wsh[6], w7 = wsh[7], w8 = wsh[8];

    // stage 2: 16 samples x 26 rows x 7 col-groups (4 outputs each, last 2)
    #pragma unroll 1
    for (int i = tid; i < CSAMP * 182; i += 256) {
        const int s  = i / 182;
        const int r  = i - s * 182;
        const int oi = r / 7;
        const int g  = r - oi * 7;
        const int oj = g * 4;

        const float* p = xs + s * 784 + oi * 28 + oj;
        float4 a0 = *(const float4*)(p);
        float4 a1 = *(const float4*)(p + 4);
        float4 b0 = *(const float4*)(p + 28);
        float4 b1 = *(const float4*)(p + 32);
        float4 c0 = *(const float4*)(p + 56);
        float4 c1 = *(const float4*)(p + 60);
        const float ra[8] = {a0.x, a0.y, a0.z, a0.w, a1.x, a1.y, a1.z, a1.w};
        const float rb[8] = {b0.x, b0.y, b0.z, b0.w, b1.x, b1.y, b1.z, b1.w};
        const float rc[8] = {c0.x, c0.y, c0.z, c0.w, c1.x, c1.y, c1.z, c1.w};

        float sums[4];
        #pragma unroll
        for (int j = 0; j < 4; ++j) {
            float sum = ra[j] * w0;
            sum = fmaf(ra[j + 1], w1, sum); sum = fmaf(ra[j + 2], w2, sum);
            sum = fmaf(rb[j],     w3, sum); sum = fmaf(rb[j + 1], w4, sum);
            sum = fmaf(rb[j + 2], w5, sum); sum = fmaf(rc[j],     w6, sum);
            sum = fmaf(rc[j + 1], w7, sum); sum = fmaf(rc[j + 2], w8, sum);
            sums[j] = sum;
        }
        const int base = s * 704 + oi * 26 + oj;   // even -> 4B aligned
        *(uint32_t*)(oh + base) =
            pack_h2(__float2half_rn(sums[0]), __float2half_rn(sums[1]));
        if (g < 6)
            *(uint32_t*)(oh + base + 2) =
                pack_h2(__float2half_rn(sums[2]), __float2half_rn(sums[3]));
    }

    // zero pad cols 676..703 (14 uints per sample)
    #pragma unroll
    for (int i = tid; i < CSAMP * 14; i += 256) {
        const int s = i / 14, k = i - s * 14;
        *(uint32_t*)(oh + s * 704 + 676 + k * 2) = 0u;
    }
    __syncthreads();

    // stage 3: uint4 copy out (16 samples x 88 uint4)
    uint4* g = (uint4*)(cout + (size_t)blockIdx.x * CSAMP * K1P);
    const uint4* sh = (const uint4*)oh;
    #pragma unroll
    for (int i = tid; i < CSAMP * 88; i += 256)
        g[i] = sh[i];
}

// ---------------------------------------------------------------------------
// Weight split: fp32 [N,Ks] -> fp16 hi/lo [N,Kd] zero-padded.
// ---------------------------------------------------------------------------
__global__ void wconv_kernel(const float* __restrict__ src, int N, int Ks, int Kd,
                             __half* __restrict__ hi,
                             __half* __restrict__ lo)
{
    int i = blockIdx.x * blockDim.x + threadIdx.x;
    if (i >= N * Kd) return;
    int n = i / Kd, k = i - n * Kd;
    float v = (k < Ks) ? src[(size_t)n * Ks + k] : 0.f;
    __half h = __float2half_rn(v);
    hi[i] = h;
    lo[i] = __float2half_rn(v - __half2float(h));
}

// ---------------------------------------------------------------------------
// mma.sync fp16 GEMM, weight-split: C[m,n] = act( sum_k A[m,k]*W[n,k] + b[n] )
// A: single fp16 [M,K]; W: fp16 hi/lo [N,K]. 2 MMAs per fragment pair.
// CTA: 64x128 tile, 4 warps (32x64 each), 128 threads, BK=64,
// double-buffered cp.async (~81KB smem -> 2 CTAs/SM).
// HALF_OUT=true: fp16 out; else fp32 out. M%64==0, N%128==0, K%64==0.
// ---------------------------------------------------------------------------
#define SM_A    0
#define SM_B_HI 8192
#define SM_B_LO 24576
#define BUF_STRIDE 40960
#define SM_BIAS (2 * BUF_STRIDE)
#define SMEM_SZ (SM_BIAS + 512)

template <bool RELU, bool HALF_OUT>
__global__ void __launch_bounds__(128, 2)
gemm_mma(const __half* __restrict__ A,
         const __half* __restrict__ Bh, const __half* __restrict__ Bl,
         const float* __restrict__ bias,
         void* __restrict__ outp,
         int N, int K)
{
    extern __shared__ __align__(1024) char smem[];
    const uint32_t sb = smem_u32(smem);
    const int tid  = threadIdx.x;
    const int wid  = tid >> 5;
    const int lane = tid & 31;
    const int m0   = blockIdx.y * 64;
    const int n0   = blockIdx.x * 128;
    float* bs = (float*)(smem + SM_BIAS);

    bs[tid] = bias[n0 + tid];

    // ---- loader addressing (128B rows, SW128) ----
    uint32_t soA[4]; size_t gaOff[4];
    #pragma unroll
    for (int i = 0; i < 4; ++i) {
        const int idx = tid + 128 * i;
        const int row = idx >> 3, ch = idx & 7;
        soA[i]  = SWZ128((uint32_t)row * 128 + ch * 16);
        gaOff[i] = (size_t)(m0 + row) * K + ch * 8;
    }
    uint32_t soB[8]; size_t gbOff[8];
    #pragma unroll
    for (int i = 0; i < 8; ++i) {
        const int idx = tid + 128 * i;
        const int row = idx >> 3, ch = idx & 7;
        soB[i]  = SWZ128((uint32_t)row * 128 + ch * 16);
        gbOff[i] = (size_t)(n0 + row) * K + ch * 8;
    }

    // prefetch tile 0 into buffer 0
    #pragma unroll
    for (int i = 0; i < 4; ++i)
        CP_ASYNC16(sb + SM_A + soA[i], A + gaOff[i]);
    #pragma unroll
    for (int i = 0; i < 8; ++i) {
        CP_ASYNC16(sb + SM_B_HI + soB[i], Bh + gbOff[i]);
        CP_ASYNC16(sb + SM_B_LO + soB[i], Bl + gbOff[i]);
    }
    CP_COMMIT();

    // ---- warp tiling: wm in {0,1} (32 rows), wn in {0,1} (64 cols) ----
    const int wm = wid & 1;
    const int wn = wid >> 1;
    const int lrow  = lane & 15;
    const int lhalf = (lane >> 4) * 16;

    float acc[2][8][4];
    #pragma unroll
    for (int mi = 0; mi < 2; ++mi)
        #pragma unroll
        for (int nj = 0; nj < 8; ++nj)
            #pragma unroll
            for (int q = 0; q < 4; ++q) acc[mi][nj][q] = 0.f;

    int buf = 0;
    for (int kt = 0; kt < K; kt += 64) {
        CP_WAIT0();
        __syncthreads();

        if (kt + 64 < K) {
            const uint32_t nb = sb + (buf ^ 1) * BUF_STRIDE;
            #pragma unroll
            for (int i = 0; i < 4; ++i)
                CP_ASYNC16(nb + SM_A + soA[i], A + gaOff[i] + kt + 64);
            #pragma unroll
            for (int i = 0; i < 8; ++i) {
                CP_ASYNC16(nb + SM_B_HI + soB[i], Bh + gbOff[i] + kt + 64);
                CP_ASYNC16(nb + SM_B_LO + soB[i], Bl + gbOff[i] + kt + 64);
            }
            CP_COMMIT();
        }

        const uint32_t cb = sb + buf * BUF_STRIDE;
        #pragma unroll
        for (int ks = 0; ks < 4; ++ks) {
            const uint32_t kbyte = ks * 32 + lhalf;
            uint32_t av[2][4];
            #pragma unroll
            for (int mi = 0; mi < 2; ++mi) {
                const uint32_t row = wm * 32 + mi * 16 + lrow;
                const uint32_t off = SWZ128(row * 128 + kbyte);
                LDSM_X4(av[mi], cb + SM_A + off);
            }
            uint32_t bh[4][4], bl[4][4];
            #pragma unroll
            for (int g = 0; g < 4; ++g) {
                const uint32_t row = wn * 64 + g * 16 + lrow;
                const uint32_t off = SWZ128(row * 128 + kbyte);
                LDSM_X4(bh[g], cb + SM_B_HI + off);
                LDSM_X4(bl[g], cb + SM_B_LO + off);
            }
            #pragma unroll
            for (int mi = 0; mi < 2; ++mi) {
                #pragma unroll
                for (int nj = 0; nj < 8; ++nj) {
                    const int g = nj >> 1, h = nj & 1;
                    MMA_F16(acc[mi][nj], av[mi], bh[g][h], bh[g][h + 2]);
                    MMA_F16(acc[mi][nj], av[mi], bl[g][h], bl[g][h + 2]);
                }
            }
        }
        __syncthreads();
        buf ^= 1;
    }

    // ---- epilogue: bias (+relu), direct global stores ----
    const int qr = lane >> 2;
    const int qc = (lane & 3) * 2;
    #pragma unroll
    for (int mi = 0; mi < 2; ++mi) {
        #pragma unroll
        for (int nj = 0; nj < 8; ++nj) {
            const int col = wn * 64 + nj * 8 + qc;
            const float b0 = bs[col], b1 = bs[col + 1];
            #pragma unroll
            for (int half = 0; half < 2; ++half) {
                const int row = wm * 32 + mi * 16 + qr + half * 8;
                float v0 = acc[mi][nj][half * 2 + 0] + b0;
                float v1 = acc[mi][nj][half * 2 + 1] + b1;
                if (RELU) { v0 = fmaxf(v0, 0.f); v1 = fmaxf(v1, 0.f); }
                const size_t g = (size_t)(m0 + row) * N + n0 + col;
                if (HALF_OUT) {
                    *(uint32_t*)((__half*)outp + g) =
                        pack_h2(__float2half_rn(v0), __float2half_rn(v1));
                } else {
                    *(float2*)((float*)outp + g) = make_float2(v0, v1);
                }
            }
        }
    }
}

// ---------------------------------------------------------------------------
// Head: out[m,0..9] = h3[m,:] @ w4^T + b4 (K=256, N=10). fp16 input.
// ---------------------------------------------------------------------------
__global__ void __launch_bounds__(256)
head_kernel(const __half* __restrict__ h3,
            const float* __restrict__ w4,
            const float* __restrict__ b4,
            float* __restrict__ out)
{
    __shared__ float ws[10 * 256];
    __shared__ float bsh[10];
    const int tid = threadIdx.x;
    #pragma unroll
    for (int i = tid; i < 2560; i += 256) ws[i] = w4[i];
    if (tid < 10) bsh[tid] = b4[tid];
    __syncthreads();

    const int warp = tid >> 5;
    const int lane = tid & 31;
    const int row  = blockIdx.x * 8 + warp;

    float acc[10];
    #pragma unroll
    for (int j = 0; j < 10; ++j) acc[j] = 0.f;

    const __half2* hr = (const __half2*)(h3 + (size_t)row * 256);
    #pragma unroll
    for (int t = 0; t < 4; ++t) {
        const int i2 = t * 32 + lane;          // half2 index: k = 2*i2
        float2 xv = __half22float2(hr[i2]);
        #pragma unroll
        for (int j = 0; j < 10; ++j) {
            acc[j] = fmaf(xv.x, ws[j * 256 + i2 * 2],     acc[j]);
            acc[j] = fmaf(xv.y, ws[j * 256 + i2 * 2 + 1], acc[j]);
        }
    }
    #pragma unroll
    for (int j = 0; j < 10; ++j) {
        #pragma unroll
        for (int off = 16; off > 0; off >>= 1)
            acc[j] += __shfl_xor_sync(0xffffffffu, acc[j], off);
    }
    if (lane == 0) {
        #pragma unroll
        for (int j = 0; j < 10; ++j)
            out[(size_t)row * 10 + j] = acc[j] + bsh[j];
    }
}

// ---------------------------------------------------------------------------
// Launch
// ---------------------------------------------------------------------------
extern "C" void kernel_launch(void* const* d_in, const int* in_sizes, int n_in,
                              void* d_out, int out_size)
{
    const float* x  = (const float*)d_in[0];
    const float* wc = (const float*)d_in[1];
    const float* w1 = (const float*)d_in[2];
    const float* b1 = (const float*)d_in[3];
    const float* w2 = (const float*)d_in[4];
    const float* b2 = (const float*)d_in[5];
    const float* w3 = (const float*)d_in[6];
    const float* b3 = (const float*)d_in[7];
    const float* w4 = (const float*)d_in[8];
    const float* b4 = (const float*)d_in[9];
    float* out = (float*)d_out;

    __half *c, *h1, *h2, *h3;
    __half *w1h, *w1l, *w2h, *w2l, *w3h, *w3l;
    cudaGetSymbolAddress((void**)&c,   g_c);
    cudaGetSymbolAddress((void**)&h1,  g_h1);
    cudaGetSymbolAddress((void**)&h2,  g_h2);
    cudaGetSymbolAddress((void**)&h3,  g_h3);
    cudaGetSymbolAddress((void**)&w1h, g_w1_hi);
    cudaGetSymbolAddress((void**)&w1l, g_w1_lo);
    cudaGetSymbolAddress((void**)&w2h, g_w2_hi);
    cudaGetSymbolAddress((void**)&w2l, g_w2_lo);
    cudaGetSymbolAddress((void**)&w3h, g_w3_hi);
    cudaGetSymbolAddress((void**)&w3l, g_w3_lo);

    cudaFuncSetAttribute(conv_kernel,
                         cudaFuncAttributeMaxDynamicSharedMemorySize, CONV_SMEM);
    cudaFuncSetAttribute(gemm_mma<true, true>,
                         cudaFuncAttributeMaxDynamicSharedMemorySize, SMEM_SZ);
    cudaFuncSetAttribute(gemm_mma<false, true>,
                         cudaFuncAttributeMaxDynamicSharedMemorySize, SMEM_SZ);

    wconv_kernel<<<(128 * K1P + 255) / 256, 256>>>(w1, 128, 676, K1P, w1h, w1l);
    wconv_kernel<<<(512 * 128 + 255) / 256, 256>>>(w2, 512, 128, 128, w2h, w2l);
    wconv_kernel<<<(256 * 512 + 255) / 256, 256>>>(w3, 256, 512, 512, w3h, w3l);

    conv_kernel<<<BATCH / CSAMP, 256, CONV_SMEM>>>(x, wc, c);

    // L1: [B,704] x [128,704]^T -> relu -> h1 (fp16)
    gemm_mma<true, true><<<dim3(1, BATCH / 64), 128, SMEM_SZ>>>(
        c, w1h, w1l, b1, h1, 128, K1P);
    // L2: [B,128] x [512,128]^T -> relu -> h2 (fp16)
    gemm_mma<true, true><<<dim3(4, BATCH / 64), 128, SMEM_SZ>>>(
        h1, w2h, w2l, b2, h2, 512, 128);
    // L3: [B,512] x [256,512]^T -> relu -> h3 (fp16)
    gemm_mma<true, true><<<dim3(2, BATCH / 64), 128, SMEM_SZ>>>(
        h2, w3h, w3l, b3, h3, 256, 512);
    // L4
    head_kernel<<<BATCH / 8, 256>>>(h3, w4, b4, out);
}

// round 9
// speedup vs baseline: 2.0351x; 1.3910x over previous
#include <cuda_runtime.h>
#include <cuda_fp16.h>
#include <cstdint>

// ---------------------------------------------------------------------------
// DigitConvolutionalModel via mma.sync fp16 GEMMs (single fp16 weights).
// R9: weight hi/lo split dropped (error model: each fp16 tensor rounding adds
// ~2.4e-4 in quadrature; predicted total ~5.5e-4 < 1e-3). h3 back to fp32.
// Conv reads x straight from gmem (L1-cached reuse), smem only for output.
// ---------------------------------------------------------------------------

#define BATCH 65536
#define K1P   704

// ---- scratch (__device__ globals; no allocations allowed) ----
__device__ __half g_c [BATCH * K1P];
__device__ __half g_h1[BATCH * 128];
__device__ __half g_h2[BATCH * 512];
__device__ float  g_h3[BATCH * 256];
__device__ __half g_w1[128 * K1P];
__device__ __half g_w2[512 * 128];
__device__ __half g_w3[256 * 512];

// ---------------------------------------------------------------------------
// helpers
// ---------------------------------------------------------------------------
__device__ __forceinline__ uint32_t smem_u32(const void* p) {
    uint32_t a;
    asm("{ .reg .u64 t; cvta.to.shared.u64 t, %1; cvt.u32.u64 %0, t; }"
        : "=r"(a) : "l"(p));
    return a;
}
#define SWZ128(off) ((off) ^ (((off) >> 3) & 0x70))

#define CP_ASYNC16(saddr, gptr) \
    asm volatile("cp.async.cg.shared.global [%0], [%1], 16;" \
                 :: "r"(saddr), "l"(gptr) : "memory")
#define CP_COMMIT() asm volatile("cp.async.commit_group;" ::: "memory")
#define CP_WAIT0()  asm volatile("cp.async.wait_group 0;" ::: "memory")

#define LDSM_X4(r, addr) \
    asm volatile("ldmatrix.sync.aligned.m8n8.x4.shared.b16 {%0,%1,%2,%3}, [%4];" \
                 : "=r"((r)[0]), "=r"((r)[1]), "=r"((r)[2]), "=r"((r)[3]) \
                 : "r"(addr))

#define MMA_F16(d, a, b0, b1) \
    asm volatile("mma.sync.aligned.m16n8k16.row.col.f32.f16.f16.f32 " \
                 "{%0,%1,%2,%3}, {%4,%5,%6,%7}, {%8,%9}, {%0,%1,%2,%3};" \
                 : "+f"((d)[0]), "+f"((d)[1]), "+f"((d)[2]), "+f"((d)[3]) \
                 : "r"((a)[0]), "r"((a)[1]), "r"((a)[2]), "r"((a)[3]), \
                   "r"(b0), "r"(b1))

__device__ __forceinline__ unsigned pack_h2(__half a, __half b) {
    return (unsigned)__half_as_ushort(a) | ((unsigned)__half_as_ushort(b) << 16);
}

// ---------------------------------------------------------------------------
// Conv v5: 16 samples/CTA. x read directly from gmem via LDG.128 (per-CTA
// 50KB working set stays in L1; 3x row reuse absorbed there). Output staged
// in smem (22.5KB), uint4 copy out. K padded to 704.
// ---------------------------------------------------------------------------
#define CSAMP 16

__global__ void __launch_bounds__(256)
conv_kernel(const float* __restrict__ x,
            const float* __restrict__ wc,
            __half* __restrict__ cout)
{
    __shared__ __align__(16) __half oh[CSAMP][704];
    __shared__ float wsh[9];

    const int tid = threadIdx.x;
    if (tid < 9) wsh[tid] = wc[tid];
    __syncthreads();

    const float w0 = wsh[0], w1 = wsh[1], w2 = wsh[2];
    const float w3 = wsh[3], w4 = wsh[4], w5 = wsh[5];
    const float w6 = wsh[6], w7 = wsh[7], w8 = wsh[8];

    const float* xb = x + (size_t)blockIdx.x * CSAMP * 784;

    // 16 samples x 26 rows x 7 col-groups (4 outputs each; last group 2)
    #pragma unroll 1
    for (int i = tid; i < CSAMP * 182; i += 256) {
        const int s  = i / 182;
        const int r  = i - s * 182;
        const int oi = r / 7;
        const int g  = r - oi * 7;
        const int oj = g * 4;

        const float* p = xb + s * 784 + oi * 28 + oj;
        float4 a0 = *(const float4*)(p);
        float4 b0 = *(const float4*)(p + 28);
        float4 c0 = *(const float4*)(p + 56);
        float4 a1 = make_float4(0.f, 0.f, 0.f, 0.f), b1 = a1, c1 = a1;
        if (g < 6) {                       // avoid 16B overread on last group
            a1 = *(const float4*)(p + 4);
            b1 = *(const float4*)(p + 32);
            c1 = *(const float4*)(p + 60);
        }
        const float ra[8] = {a0.x, a0.y, a0.z, a0.w, a1.x, a1.y, a1.z, a1.w};
        const float rb[8] = {b0.x, b0.y, b0.z, b0.w, b1.x, b1.y, b1.z, b1.w};
        const float rc[8] = {c0.x, c0.y, c0.z, c0.w, c1.x, c1.y, c1.z, c1.w};

        float sums[4];
        #pragma unroll
        for (int j = 0; j < 4; ++j) {
            float sum = ra[j] * w0;
            sum = fmaf(ra[j + 1], w1, sum); sum = fmaf(ra[j + 2], w2, sum);
            sum = fmaf(rb[j],     w3, sum); sum = fmaf(rb[j + 1], w4, sum);
            sum = fmaf(rb[j + 2], w5, sum); sum = fmaf(rc[j],     w6, sum);
            sum = fmaf(rc[j + 1], w7, sum); sum = fmaf(rc[j + 2], w8, sum);
            sums[j] = sum;
        }
        const int base = s * 704 + oi * 26 + oj;   // even -> 4B aligned
        *(uint32_t*)(&oh[0][0] + base) =
            pack_h2(__float2half_rn(sums[0]), __float2half_rn(sums[1]));
        if (g < 6)
            *(uint32_t*)(&oh[0][0] + base + 2) =
                pack_h2(__float2half_rn(sums[2]), __float2half_rn(sums[3]));
    }

    // zero pad cols 676..703
    #pragma unroll
    for (int i = tid; i < CSAMP * 14; i += 256) {
        const int s = i / 14, k = i - s * 14;
        *(uint32_t*)(&oh[s][676] + k * 2) = 0u;
    }
    __syncthreads();

    // uint4 copy out (16 samples x 88 uint4)
    uint4* g = (uint4*)(cout + (size_t)blockIdx.x * CSAMP * K1P);
    const uint4* sh = (const uint4*)&oh[0][0];
    #pragma unroll
    for (int i = tid; i < CSAMP * 88; i += 256)
        g[i] = sh[i];
}

// ---------------------------------------------------------------------------
// Weight cast: fp32 [N,Ks] -> fp16 [N,Kd] zero-padded.
// ---------------------------------------------------------------------------
__global__ void wcast_kernel(const float* __restrict__ src, int N, int Ks, int Kd,
                             __half* __restrict__ dst)
{
    int i = blockIdx.x * blockDim.x + threadIdx.x;
    if (i >= N * Kd) return;
    int n = i / Kd, k = i - n * Kd;
    float v = (k < Ks) ? src[(size_t)n * Ks + k] : 0.f;
    dst[i] = __float2half_rn(v);
}

// ---------------------------------------------------------------------------
// mma.sync fp16 GEMM: C[m,n] = act( sum_k A[m,k]*W[n,k] + bias[n] )
// Single fp16 A and W. CTA: 64x128 tile, 4 warps (32x64 each), 128 threads,
// BK=64, double-buffered cp.async (~49KB smem -> 4 CTAs/SM).
// HALF_OUT=true: fp16 out; else fp32 out. M%64==0, N%128==0, K%64==0.
// ---------------------------------------------------------------------------
#define SM_A    0
#define SM_B    8192
#define BUF_STRIDE 24576
#define SM_BIAS (2 * BUF_STRIDE)
#define SMEM_SZ (SM_BIAS + 512)

template <bool RELU, bool HALF_OUT>
__global__ void __launch_bounds__(128)
gemm_mma(const __half* __restrict__ A,
         const __half* __restrict__ B,
         const float* __restrict__ bias,
         void* __restrict__ outp,
         int N, int K)
{
    extern __shared__ __align__(1024) char smem[];
    const uint32_t sb = smem_u32(smem);
    const int tid  = threadIdx.x;
    const int wid  = tid >> 5;
    const int lane = tid & 31;
    const int m0   = blockIdx.y * 64;
    const int n0   = blockIdx.x * 128;
    float* bs = (float*)(smem + SM_BIAS);

    bs[tid] = bias[n0 + tid];

    // ---- loader addressing (128B rows, SW128) ----
    uint32_t soA[4]; size_t gaOff[4];
    #pragma unroll
    for (int i = 0; i < 4; ++i) {
        const int idx = tid + 128 * i;
        const int row = idx >> 3, ch = idx & 7;
        soA[i]  = SWZ128((uint32_t)row * 128 + ch * 16);
        gaOff[i] = (size_t)(m0 + row) * K + ch * 8;
    }
    uint32_t soB[8]; size_t gbOff[8];
    #pragma unroll
    for (int i = 0; i < 8; ++i) {
        const int idx = tid + 128 * i;
        const int row = idx >> 3, ch = idx & 7;
        soB[i]  = SWZ128((uint32_t)row * 128 + ch * 16);
        gbOff[i] = (size_t)(n0 + row) * K + ch * 8;
    }

    // prefetch tile 0 into buffer 0
    #pragma unroll
    for (int i = 0; i < 4; ++i)
        CP_ASYNC16(sb + SM_A + soA[i], A + gaOff[i]);
    #pragma unroll
    for (int i = 0; i < 8; ++i)
        CP_ASYNC16(sb + SM_B + soB[i], B + gbOff[i]);
    CP_COMMIT();

    // ---- warp tiling: wm in {0,1} (32 rows), wn in {0,1} (64 cols) ----
    const int wm = wid & 1;
    const int wn = wid >> 1;
    const int lrow  = lane & 15;
    const int lhalf = (lane >> 4) * 16;

    float acc[2][8][4];
    #pragma unroll
    for (int mi = 0; mi < 2; ++mi)
        #pragma unroll
        for (int nj = 0; nj < 8; ++nj)
            #pragma unroll
            for (int q = 0; q < 4; ++q) acc[mi][nj][q] = 0.f;

    int buf = 0;
    for (int kt = 0; kt < K; kt += 64) {
        CP_WAIT0();
        __syncthreads();

        if (kt + 64 < K) {
            const uint32_t nb = sb + (buf ^ 1) * BUF_STRIDE;
            #pragma unroll
            for (int i = 0; i < 4; ++i)
                CP_ASYNC16(nb + SM_A + soA[i], A + gaOff[i] + kt + 64);
            #pragma unroll
            for (int i = 0; i < 8; ++i)
                CP_ASYNC16(nb + SM_B + soB[i], B + gbOff[i] + kt + 64);
            CP_COMMIT();
        }

        const uint32_t cb = sb + buf * BUF_STRIDE;
        #pragma unroll
        for (int ks = 0; ks < 4; ++ks) {
            const uint32_t kbyte = ks * 32 + lhalf;
            uint32_t av[2][4];
            #pragma unroll
            for (int mi = 0; mi < 2; ++mi) {
                const uint32_t row = wm * 32 + mi * 16 + lrow;
                const uint32_t off = SWZ128(row * 128 + kbyte);
                LDSM_X4(av[mi], cb + SM_A + off);
            }
            uint32_t bv[4][4];
            #pragma unroll
            for (int g = 0; g < 4; ++g) {
                const uint32_t row = wn * 64 + g * 16 + lrow;
                const uint32_t off = SWZ128(row * 128 + kbyte);
                LDSM_X4(bv[g], cb + SM_B + off);
            }
            #pragma unroll
            for (int mi = 0; mi < 2; ++mi) {
                #pragma unroll
                for (int nj = 0; nj < 8; ++nj) {
                    const int g = nj >> 1, h = nj & 1;
                    MMA_F16(acc[mi][nj], av[mi], bv[g][h], bv[g][h + 2]);
                }
            }
        }
        __syncthreads();
        buf ^= 1;
    }

    // ---- epilogue: bias (+relu), direct global stores ----
    const int qr = lane >> 2;
    const int qc = (lane & 3) * 2;
    #pragma unroll
    for (int mi = 0; mi < 2; ++mi) {
        #pragma unroll
        for (int nj = 0; nj < 8; ++nj) {
            const int col = wn * 64 + nj * 8 + qc;
            const float b0 = bs[col], b1 = bs[col + 1];
            #pragma unroll
            for (int half = 0; half < 2; ++half) {
                const int row = wm * 32 + mi * 16 + qr + half * 8;
                float v0 = acc[mi][nj][half * 2 + 0] + b0;
                float v1 = acc[mi][nj][half * 2 + 1] + b1;
                if (RELU) { v0 = fmaxf(v0, 0.f); v1 = fmaxf(v1, 0.f); }
                const size_t g = (size_t)(m0 + row) * N + n0 + col;
                if (HALF_OUT) {
                    *(uint32_t*)((__half*)outp + g) =
                        pack_h2(__float2half_rn(v0), __float2half_rn(v1));
                } else {
                    *(float2*)((float*)outp + g) = make_float2(v0, v1);
                }
            }
        }
    }
}

// ---------------------------------------------------------------------------
// Head: out[m,0..9] = h3[m,:] @ w4^T + b4 (K=256, N=10). fp32 input.
// ---------------------------------------------------------------------------
__global__ void __launch_bounds__(256)
head_kernel(const float* __restrict__ h3,
            const float* __restrict__ w4,
            const float* __restrict__ b4,
            float* __restrict__ out)
{
    __shared__ float ws[10 * 256];
    __shared__ float bsh[10];
    const int tid = threadIdx.x;
    #pragma unroll
    for (int i = tid; i < 2560; i += 256) ws[i] = w4[i];
    if (tid < 10) bsh[tid] = b4[tid];
    __syncthreads();

    const int warp = tid >> 5;
    const int lane = tid & 31;
    const int row  = blockIdx.x * 8 + warp;

    float acc[10];
    #pragma unroll
    for (int j = 0; j < 10; ++j) acc[j] = 0.f;

    const float* hr = h3 + (size_t)row * 256;
    #pragma unroll
    for (int t = 0; t < 8; ++t) {
        float xv = hr[t * 32 + lane];
        #pragma unroll
        for (int j = 0; j < 10; ++j)
            acc[j] = fmaf(xv, ws[j * 256 + t * 32 + lane], acc[j]);
    }
    #pragma unroll
    for (int j = 0; j < 10; ++j) {
        #pragma unroll
        for (int off = 16; off > 0; off >>= 1)
            acc[j] += __shfl_xor_sync(0xffffffffu, acc[j], off);
    }
    if (lane == 0) {
        #pragma unroll
        for (int j = 0; j < 10; ++j)
            out[(size_t)row * 10 + j] = acc[j] + bsh[j];
    }
}

// ---------------------------------------------------------------------------
// Launch
// ---------------------------------------------------------------------------
extern "C" void kernel_launch(void* const* d_in, const int* in_sizes, int n_in,
                              void* d_out, int out_size)
{
    const float* x  = (const float*)d_in[0];
    const float* wc = (const float*)d_in[1];
    const float* w1 = (const float*)d_in[2];
    const float* b1 = (const float*)d_in[3];
    const float* w2 = (const float*)d_in[4];
    const float* b2 = (const float*)d_in[5];
    const float* w3 = (const float*)d_in[6];
    const float* b3 = (const float*)d_in[7];
    const float* w4 = (const float*)d_in[8];
    const float* b4 = (const float*)d_in[9];
    float* out = (float*)d_out;

    __half *c, *h1, *h2, *w1c, *w2c, *w3c;
    float* h3;
    cudaGetSymbolAddress((void**)&c,   g_c);
    cudaGetSymbolAddress((void**)&h1,  g_h1);
    cudaGetSymbolAddress((void**)&h2,  g_h2);
    cudaGetSymbolAddress((void**)&h3,  g_h3);
    cudaGetSymbolAddress((void**)&w1c, g_w1);
    cudaGetSymbolAddress((void**)&w2c, g_w2);
    cudaGetSymbolAddress((void**)&w3c, g_w3);

    cudaFuncSetAttribute(gemm_mma<true, true>,
                         cudaFuncAttributeMaxDynamicSharedMemorySize, SMEM_SZ);
    cudaFuncSetAttribute(gemm_mma<true, false>,
                         cudaFuncAttributeMaxDynamicSharedMemorySize, SMEM_SZ);

    wcast_kernel<<<(128 * K1P + 255) / 256, 256>>>(w1, 128, 676, K1P, w1c);
    wcast_kernel<<<(512 * 128 + 255) / 256, 256>>>(w2, 512, 128, 128, w2c);
    wcast_kernel<<<(256 * 512 + 255) / 256, 256>>>(w3, 256, 512, 512, w3c);

    conv_kernel<<<BATCH / CSAMP, 256>>>(x, wc, c);

    // L1: [B,704] x [128,704]^T -> relu -> h1 (fp16)
    gemm_mma<true, true><<<dim3(1, BATCH / 64), 128, SMEM_SZ>>>(
        c, w1c, b1, h1, 128, K1P);
    // L2: [B,128] x [512,128]^T -> relu -> h2 (fp16)
    gemm_mma<true, true><<<dim3(4, BATCH / 64), 128, SMEM_SZ>>>(
        h1, w2c, b2, h2, 512, 128);
    // L3: [B,512] x [256,512]^T -> relu -> h3 (fp32)
    gemm_mma<true, false><<<dim3(2, BATCH / 64), 128, SMEM_SZ>>>(
        h2, w3c, b3, h3, 256, 512);
    // L4
    head_kernel<<<BATCH / 8, 256>>>(h3, w4, b4, out);
}

// round 10
// speedup vs baseline: 2.1006x; 1.0322x over previous
#include <cuda_runtime.h>
#include <cuda_fp16.h>
#include <cstdint>

// ---------------------------------------------------------------------------
// DigitConvolutionalModel via mma.sync fp16 GEMMs (single fp16 weights).
// R10: head (fc 256->10) fused into L3 epilogue via smem stage + warp
// reduce + atomicAdd into out (pre-initialized with b4). h3 buffer gone.
// ---------------------------------------------------------------------------

#define BATCH 65536
#define K1P   704

// ---- scratch (__device__ globals; no allocations allowed) ----
__device__ __half g_c [BATCH * K1P];
__device__ __half g_h1[BATCH * 128];
__device__ __half g_h2[BATCH * 512];
__device__ __half g_w1[128 * K1P];
__device__ __half g_w2[512 * 128];
__device__ __half g_w3[256 * 512];

// ---------------------------------------------------------------------------
// helpers
// ---------------------------------------------------------------------------
__device__ __forceinline__ uint32_t smem_u32(const void* p) {
    uint32_t a;
    asm("{ .reg .u64 t; cvta.to.shared.u64 t, %1; cvt.u32.u64 %0, t; }"
        : "=r"(a) : "l"(p));
    return a;
}
#define SWZ128(off) ((off) ^ (((off) >> 3) & 0x70))

#define CP_ASYNC16(saddr, gptr) \
    asm volatile("cp.async.cg.shared.global [%0], [%1], 16;" \
                 :: "r"(saddr), "l"(gptr) : "memory")
#define CP_COMMIT() asm volatile("cp.async.commit_group;" ::: "memory")
#define CP_WAIT0()  asm volatile("cp.async.wait_group 0;" ::: "memory")

#define LDSM_X4(r, addr) \
    asm volatile("ldmatrix.sync.aligned.m8n8.x4.shared.b16 {%0,%1,%2,%3}, [%4];" \
                 : "=r"((r)[0]), "=r"((r)[1]), "=r"((r)[2]), "=r"((r)[3]) \
                 : "r"(addr))

#define MMA_F16(d, a, b0, b1) \
    asm volatile("mma.sync.aligned.m16n8k16.row.col.f32.f16.f16.f32 " \
                 "{%0,%1,%2,%3}, {%4,%5,%6,%7}, {%8,%9}, {%0,%1,%2,%3};" \
                 : "+f"((d)[0]), "+f"((d)[1]), "+f"((d)[2]), "+f"((d)[3]) \
                 : "r"((a)[0]), "r"((a)[1]), "r"((a)[2]), "r"((a)[3]), \
                   "r"(b0), "r"(b1))

__device__ __forceinline__ unsigned pack_h2(__half a, __half b) {
    return (unsigned)__half_as_ushort(a) | ((unsigned)__half_as_ushort(b) << 16);
}

// ---------------------------------------------------------------------------
// Conv: 16 samples/CTA. x read directly from gmem via LDG.128 (L1-cached
// reuse). Output staged in smem, uint4 copy out. K padded to 704.
// ---------------------------------------------------------------------------
#define CSAMP 16

__global__ void __launch_bounds__(256)
conv_kernel(const float* __restrict__ x,
            const float* __restrict__ wc,
            __half* __restrict__ cout)
{
    __shared__ __align__(16) __half oh[CSAMP][704];
    __shared__ float wsh[9];

    const int tid = threadIdx.x;
    if (tid < 9) wsh[tid] = wc[tid];
    __syncthreads();

    const float w0 = wsh[0], w1 = wsh[1], w2 = wsh[2];
    const float w3 = wsh[3], w4 = wsh[4], w5 = wsh[5];
    const float w6 = wsh[6], w7 = wsh[7], w8 = wsh[8];

    const float* xb = x + (size_t)blockIdx.x * CSAMP * 784;

    #pragma unroll 1
    for (int i = tid; i < CSAMP * 182; i += 256) {
        const int s  = i / 182;
        const int r  = i - s * 182;
        const int oi = r / 7;
        const int g  = r - oi * 7;
        const int oj = g * 4;

        const float* p = xb + s * 784 + oi * 28 + oj;
        float4 a0 = *(const float4*)(p);
        float4 b0 = *(const float4*)(p + 28);
        float4 c0 = *(const float4*)(p + 56);
        float4 a1 = make_float4(0.f, 0.f, 0.f, 0.f), b1 = a1, c1 = a1;
        if (g < 6) {
            a1 = *(const float4*)(p + 4);
            b1 = *(const float4*)(p + 32);
            c1 = *(const float4*)(p + 60);
        }
        const float ra[8] = {a0.x, a0.y, a0.z, a0.w, a1.x, a1.y, a1.z, a1.w};
        const float rb[8] = {b0.x, b0.y, b0.z, b0.w, b1.x, b1.y, b1.z, b1.w};
        const float rc[8] = {c0.x, c0.y, c0.z, c0.w, c1.x, c1.y, c1.z, c1.w};

        float sums[4];
        #pragma unroll
        for (int j = 0; j < 4; ++j) {
            float sum = ra[j] * w0;
            sum = fmaf(ra[j + 1], w1, sum); sum = fmaf(ra[j + 2], w2, sum);
            sum = fmaf(rb[j],     w3, sum); sum = fmaf(rb[j + 1], w4, sum);
            sum = fmaf(rb[j + 2], w5, sum); sum = fmaf(rc[j],     w6, sum);
            sum = fmaf(rc[j + 1], w7, sum); sum = fmaf(rc[j + 2], w8, sum);
            sums[j] = sum;
        }
        const int base = s * 704 + oi * 26 + oj;
        *(uint32_t*)(&oh[0][0] + base) =
            pack_h2(__float2half_rn(sums[0]), __float2half_rn(sums[1]));
        if (g < 6)
            *(uint32_t*)(&oh[0][0] + base + 2) =
                pack_h2(__float2half_rn(sums[2]), __float2half_rn(sums[3]));
    }

    #pragma unroll
    for (int i = tid; i < CSAMP * 14; i += 256) {
        const int s = i / 14, k = i - s * 14;
        *(uint32_t*)(&oh[s][676] + k * 2) = 0u;
    }
    __syncthreads();

    uint4* g = (uint4*)(cout + (size_t)blockIdx.x * CSAMP * K1P);
    const uint4* sh = (const uint4*)&oh[0][0];
    #pragma unroll
    for (int i = tid; i < CSAMP * 88; i += 256)
        g[i] = sh[i];
}

// ---------------------------------------------------------------------------
// Weight cast: fp32 [N,Ks] -> fp16 [N,Kd] zero-padded.
// ---------------------------------------------------------------------------
__global__ void wcast_kernel(const float* __restrict__ src, int N, int Ks, int Kd,
                             __half* __restrict__ dst)
{
    int i = blockIdx.x * blockDim.x + threadIdx.x;
    if (i >= N * Kd) return;
    int n = i / Kd, k = i - n * Kd;
    float v = (k < Ks) ? src[(size_t)n * Ks + k] : 0.f;
    dst[i] = __float2half_rn(v);
}

// ---------------------------------------------------------------------------
// out init: out[m][j] = b4[j]  (atomic partials from L3 land on top)
// ---------------------------------------------------------------------------
__global__ void init_out_kernel(const float* __restrict__ b4,
                                float* __restrict__ out)
{
    int i = blockIdx.x * blockDim.x + threadIdx.x;
    if (i >= BATCH * 10) return;
    int j = i - (i / 10) * 10;
    out[i] = b4[j];
}

// ---------------------------------------------------------------------------
// mma.sync fp16 GEMM: C[m,n] = act( sum_k A[m,k]*W[n,k] + bias[n] )
// CTA: 64x128 tile, 4 warps (32x64 each), 128 threads, BK=64,
// double-buffered cp.async (~49KB smem -> 4 CTAs/SM).
// HEAD=true: fused fc(256->10): stage relu tile in smem, warp-reduce dot
// with w4 slice, atomicAdd partials into outp (pre-init with b4).
// Else HALF_OUT picks fp16/fp32 direct store. M%64==0, N%128==0, K%64==0.
// ---------------------------------------------------------------------------
#define SM_A    0
#define SM_B    8192
#define BUF_STRIDE 24576
#define SM_BIAS (2 * BUF_STRIDE)
#define SMEM_SZ (SM_BIAS + 512)

template <bool RELU, bool HALF_OUT, bool HEAD>
__global__ void __launch_bounds__(128)
gemm_mma(const __half* __restrict__ A,
         const __half* __restrict__ B,
         const float* __restrict__ bias,
         void* __restrict__ outp,
         int N, int K,
         const float* __restrict__ w4p)
{
    extern __shared__ __align__(1024) char smem[];
    const uint32_t sb = smem_u32(smem);
    const int tid  = threadIdx.x;
    const int wid  = tid >> 5;
    const int lane = tid & 31;
    const int m0   = blockIdx.y * 64;
    const int n0   = blockIdx.x * 128;
    float* bs = (float*)(smem + SM_BIAS);

    bs[tid] = bias[n0 + tid];

    // ---- loader addressing (128B rows, SW128) ----
    uint32_t soA[4]; size_t gaOff[4];
    #pragma unroll
    for (int i = 0; i < 4; ++i) {
        const int idx = tid + 128 * i;
        const int row = idx >> 3, ch = idx & 7;
        soA[i]  = SWZ128((uint32_t)row * 128 + ch * 16);
        gaOff[i] = (size_t)(m0 + row) * K + ch * 8;
    }
    uint32_t soB[8]; size_t gbOff[8];
    #pragma unroll
    for (int i = 0; i < 8; ++i) {
        const int idx = tid + 128 * i;
        const int row = idx >> 3, ch = idx & 7;
        soB[i]  = SWZ128((uint32_t)row * 128 + ch * 16);
        gbOff[i] = (size_t)(n0 + row) * K + ch * 8;
    }

    // prefetch tile 0 into buffer 0
    #pragma unroll
    for (int i = 0; i < 4; ++i)
        CP_ASYNC16(sb + SM_A + soA[i], A + gaOff[i]);
    #pragma unroll
    for (int i = 0; i < 8; ++i)
        CP_ASYNC16(sb + SM_B + soB[i], B + gbOff[i]);
    CP_COMMIT();

    // ---- warp tiling: wm in {0,1} (32 rows), wn in {0,1} (64 cols) ----
    const int wm = wid & 1;
    const int wn = wid >> 1;
    const int lrow  = lane & 15;
    const int lhalf = (lane >> 4) * 16;

    float acc[2][8][4];
    #pragma unroll
    for (int mi = 0; mi < 2; ++mi)
        #pragma unroll
        for (int nj = 0; nj < 8; ++nj)
            #pragma unroll
            for (int q = 0; q < 4; ++q) acc[mi][nj][q] = 0.f;

    int buf = 0;
    for (int kt = 0; kt < K; kt += 64) {
        CP_WAIT0();
        __syncthreads();

        if (kt + 64 < K) {
            const uint32_t nb = sb + (buf ^ 1) * BUF_STRIDE;
            #pragma unroll
            for (int i = 0; i < 4; ++i)
                CP_ASYNC16(nb + SM_A + soA[i], A + gaOff[i] + kt + 64);
            #pragma unroll
            for (int i = 0; i < 8; ++i)
                CP_ASYNC16(nb + SM_B + soB[i], B + gbOff[i] + kt + 64);
            CP_COMMIT();
        }

        const uint32_t cb = sb + buf * BUF_STRIDE;
        #pragma unroll
        for (int ks = 0; ks < 4; ++ks) {
            const uint32_t kbyte = ks * 32 + lhalf;
            uint32_t av[2][4];
            #pragma unroll
            for (int mi = 0; mi < 2; ++mi) {
                const uint32_t row = wm * 32 + mi * 16 + lrow;
                const uint32_t off = SWZ128(row * 128 + kbyte);
                LDSM_X4(av[mi], cb + SM_A + off);
            }
            uint32_t bv[4][4];
            #pragma unroll
            for (int g = 0; g < 4; ++g) {
                const uint32_t row = wn * 64 + g * 16 + lrow;
                const uint32_t off = SWZ128(row * 128 + kbyte);
                LDSM_X4(bv[g], cb + SM_B + off);
            }
            #pragma unroll
            for (int mi = 0; mi < 2; ++mi) {
                #pragma unroll
                for (int nj = 0; nj < 8; ++nj) {
                    const int g = nj >> 1, h = nj & 1;
                    MMA_F16(acc[mi][nj], av[mi], bv[g][h], bv[g][h + 2]);
                }
            }
        }
        __syncthreads();
        buf ^= 1;
    }

    const int qr = lane >> 2;
    const int qc = (lane & 3) * 2;

    if (HEAD) {
        // ---- fused head: stage relu tile, dot with w4 slice, atomicAdd ----
        float* stage = (float*)smem;               // 64 x 128 fp32 = 32KB
        float* w4s   = (float*)(smem + 32768);     // 10 x 128 fp32 = 5KB
        #pragma unroll
        for (int i = tid; i < 1280; i += 128) {
            const int j = i >> 7, ci = i & 127;
            w4s[i] = w4p[j * 256 + n0 + ci];
        }
        #pragma unroll
        for (int mi = 0; mi < 2; ++mi) {
            #pragma unroll
            for (int nj = 0; nj < 8; ++nj) {
                const int col = wn * 64 + nj * 8 + qc;
                const float b0 = bs[col], b1 = bs[col + 1];
                #pragma unroll
                for (int half = 0; half < 2; ++half) {
                    const int row = wm * 32 + mi * 16 + qr + half * 8;
                    stage[row * 128 + col]     = fmaxf(acc[mi][nj][half * 2 + 0] + b0, 0.f);
                    stage[row * 128 + col + 1] = fmaxf(acc[mi][nj][half * 2 + 1] + b1, 0.f);
                }
            }
        }
        __syncthreads();

        // hoist w4 slice into registers: w4r[j][t] = w4s[j*128 + lane + 32t]
        float w4r[10][4];
        #pragma unroll
        for (int j = 0; j < 10; ++j)
            #pragma unroll
            for (int t = 0; t < 4; ++t)
                w4r[j][t] = w4s[j * 128 + lane + 32 * t];

        float* outF = (float*)outp;
        #pragma unroll 1
        for (int rr = 0; rr < 16; ++rr) {
            const int row = wid * 16 + rr;
            float xv[4];
            #pragma unroll
            for (int t = 0; t < 4; ++t)
                xv[t] = stage[row * 128 + lane + 32 * t];
            float pj[10];
            #pragma unroll
            for (int j = 0; j < 10; ++j) {
                float s = xv[0] * w4r[j][0];
                s = fmaf(xv[1], w4r[j][1], s);
                s = fmaf(xv[2], w4r[j][2], s);
                s = fmaf(xv[3], w4r[j][3], s);
                #pragma unroll
                for (int off = 16; off > 0; off >>= 1)
                    s += __shfl_xor_sync(0xffffffffu, s, off);
                pj[j] = s;
            }
            if (lane == 0) {
                #pragma unroll
                for (int j = 0; j < 10; ++j)
                    atomicAdd(&outF[(size_t)(m0 + row) * 10 + j], pj[j]);
            }
        }
    } else {
        // ---- epilogue: bias (+relu), direct global stores ----
        #pragma unroll
        for (int mi = 0; mi < 2; ++mi) {
            #pragma unroll
            for (int nj = 0; nj < 8; ++nj) {
                const int col = wn * 64 + nj * 8 + qc;
                const float b0 = bs[col], b1 = bs[col + 1];
                #pragma unroll
                for (int half = 0; half < 2; ++half) {
                    const int row = wm * 32 + mi * 16 + qr + half * 8;
                    float v0 = acc[mi][nj][half * 2 + 0] + b0;
                    float v1 = acc[mi][nj][half * 2 + 1] + b1;
                    if (RELU) { v0 = fmaxf(v0, 0.f); v1 = fmaxf(v1, 0.f); }
                    const size_t g = (size_t)(m0 + row) * N + n0 + col;
                    if (HALF_OUT) {
                        *(uint32_t*)((__half*)outp + g) =
                            pack_h2(__float2half_rn(v0), __float2half_rn(v1));
                    } else {
                        *(float2*)((float*)outp + g) = make_float2(v0, v1);
                    }
                }
            }
        }
    }
}

// ---------------------------------------------------------------------------
// Launch
// ---------------------------------------------------------------------------
extern "C" void kernel_launch(void* const* d_in, const int* in_sizes, int n_in,
                              void* d_out, int out_size)
{
    const float* x  = (const float*)d_in[0];
    const float* wc = (const float*)d_in[1];
    const float* w1 = (const float*)d_in[2];
    const float* b1 = (const float*)d_in[3];
    const float* w2 = (const float*)d_in[4];
    const float* b2 = (const float*)d_in[5];
    const float* w3 = (const float*)d_in[6];
    const float* b3 = (const float*)d_in[7];
    const float* w4 = (const float*)d_in[8];
    const float* b4 = (const float*)d_in[9];
    float* out = (float*)d_out;

    __half *c, *h1, *h2, *w1c, *w2c, *w3c;
    cudaGetSymbolAddress((void**)&c,   g_c);
    cudaGetSymbolAddress((void**)&h1,  g_h1);
    cudaGetSymbolAddress((void**)&h2,  g_h2);
    cudaGetSymbolAddress((void**)&w1c, g_w1);
    cudaGetSymbolAddress((void**)&w2c, g_w2);
    cudaGetSymbolAddress((void**)&w3c, g_w3);

    cudaFuncSetAttribute((const void*)gemm_mma<true, true, false>,
                         cudaFuncAttributeMaxDynamicSharedMemorySize, SMEM_SZ);
    cudaFuncSetAttribute((const void*)gemm_mma<true, false, true>,
                         cudaFuncAttributeMaxDynamicSharedMemorySize, SMEM_SZ);

    wcast_kernel<<<(128 * K1P + 255) / 256, 256>>>(w1, 128, 676, K1P, w1c);
    wcast_kernel<<<(512 * 128 + 255) / 256, 256>>>(w2, 512, 128, 128, w2c);
    wcast_kernel<<<(256 * 512 + 255) / 256, 256>>>(w3, 256, 512, 512, w3c);

    conv_kernel<<<BATCH / CSAMP, 256>>>(x, wc, c);

    // out = b4 broadcast (L3 epilogue atomics accumulate on top)
    init_out_kernel<<<(BATCH * 10 + 255) / 256, 256>>>(b4, out);

    // L1: [B,704] x [128,704]^T -> relu -> h1 (fp16)
    gemm_mma<true, true, false><<<dim3(1, BATCH / 64), 128, SMEM_SZ>>>(
        c, w1c, b1, h1, 128, K1P, nullptr);
    // L2: [B,128] x [512,128]^T -> relu -> h2 (fp16)
    gemm_mma<true, true, false><<<dim3(4, BATCH / 64), 128, SMEM_SZ>>>(
        h1, w2c, b2, h2, 512, 128, nullptr);
    // L3 + head: relu([B,512] x [256,512]^T) @ w4^T + b4 -> out (atomic)
    gemm_mma<true, false, true><<<dim3(2, BATCH / 64), 128, SMEM_SZ>>>(
        h2, w3c, b3, out, 256, 512, w4);
}

// round 11
// speedup vs baseline: 2.2871x; 1.0888x over previous
#include <cuda_runtime.h>
#include <cuda_fp16.h>
#include <cstdint>

// ---------------------------------------------------------------------------
// DigitConvolutionalModel via mma.sync fp16 GEMMs (single fp16 weights).
// R11: conv folded into W1 (linear-linear fusion): h1 = relu(W1' x + b1),
// W1'[n, pixel] = sum_{taps} W1[n, out]*wc[tap], precomputed fp32 -> fp16.
// Conv kernel + conv buffer eliminated; L1 GEMM reads fp32 x directly via
// LDG->cvt->STS register-double-buffered loader. K1: 784 pad 832.
// Head (fc 256->10) stays fused into L3 epilogue (atomicAdd onto b4-init out).
// ---------------------------------------------------------------------------

#define BATCH 65536
#define K1P   832    // 784 padded to multiple of 64

// ---- scratch (__device__ globals; no allocations allowed) ----
__device__ __half g_h1[BATCH * 128];
__device__ __half g_h2[BATCH * 512];
__device__ __half g_w1[128 * K1P];      // folded conv+W1, fp16
__device__ __half g_w2[512 * 128];
__device__ __half g_w3[256 * 512];

// ---------------------------------------------------------------------------
// helpers
// ---------------------------------------------------------------------------
__device__ __forceinline__ uint32_t smem_u32(const void* p) {
    uint32_t a;
    asm("{ .reg .u64 t; cvta.to.shared.u64 t, %1; cvt.u32.u64 %0, t; }"
        : "=r"(a) : "l"(p));
    return a;
}
#define SWZ128(off) ((off) ^ (((off) >> 3) & 0x70))

#define CP_ASYNC16(saddr, gptr) \
    asm volatile("cp.async.cg.shared.global [%0], [%1], 16;" \
                 :: "r"(saddr), "l"(gptr) : "memory")
#define CP_COMMIT() asm volatile("cp.async.commit_group;" ::: "memory")
#define CP_WAIT0()  asm volatile("cp.async.wait_group 0;" ::: "memory")

#define LDSM_X4(r, addr) \
    asm volatile("ldmatrix.sync.aligned.m8n8.x4.shared.b16 {%0,%1,%2,%3}, [%4];" \
                 : "=r"((r)[0]), "=r"((r)[1]), "=r"((r)[2]), "=r"((r)[3]) \
                 : "r"(addr))

#define MMA_F16(d, a, b0, b1) \
    asm volatile("mma.sync.aligned.m16n8k16.row.col.f32.f16.f16.f32 " \
                 "{%0,%1,%2,%3}, {%4,%5,%6,%7}, {%8,%9}, {%0,%1,%2,%3};" \
                 : "+f"((d)[0]), "+f"((d)[1]), "+f"((d)[2]), "+f"((d)[3]) \
                 : "r"((a)[0]), "r"((a)[1]), "r"((a)[2]), "r"((a)[3]), \
                   "r"(b0), "r"(b1))

__device__ __forceinline__ unsigned pack_h2f(float a, float b) {
    return (unsigned)__half_as_ushort(__float2half_rn(a))
         | ((unsigned)__half_as_ushort(__float2half_rn(b)) << 16);
}

// ---------------------------------------------------------------------------
// wfold: W1'[n, pi*28+pj] = sum_{di,dj} W1[n,(pi-di)*26+(pj-dj)]*wc[3di+dj]
// fp32 exact, cast fp16, zero-pad cols 784..831.
// ---------------------------------------------------------------------------
__global__ void wfold_kernel(const float* __restrict__ w1,
                             const float* __restrict__ wc,
                             __half* __restrict__ dst)
{
    int i = blockIdx.x * blockDim.x + threadIdx.x;
    if (i >= 128 * K1P) return;
    int n = i / K1P, p = i - n * K1P;
    float sum = 0.f;
    if (p < 784) {
        int pi = p / 28, pj = p - pi * 28;
        #pragma unroll
        for (int di = 0; di < 3; ++di) {
            #pragma unroll
            for (int dj = 0; dj < 3; ++dj) {
                int oi = pi - di, oj = pj - dj;
                if (oi >= 0 && oi < 26 && oj >= 0 && oj < 26)
                    sum += w1[n * 676 + oi * 26 + oj] * wc[di * 3 + dj];
            }
        }
    }
    dst[i] = __float2half_rn(sum);
}

// ---------------------------------------------------------------------------
// Weight cast: fp32 [N,Ks] -> fp16 [N,Kd] zero-padded.
// ---------------------------------------------------------------------------
__global__ void wcast_kernel(const float* __restrict__ src, int N, int Ks, int Kd,
                             __half* __restrict__ dst)
{
    int i = blockIdx.x * blockDim.x + threadIdx.x;
    if (i >= N * Kd) return;
    int n = i / Kd, k = i - n * Kd;
    float v = (k < Ks) ? src[(size_t)n * Ks + k] : 0.f;
    dst[i] = __float2half_rn(v);
}

// ---------------------------------------------------------------------------
// out init: out[m][j] = b4[j]  (atomic partials from L3 land on top)
// ---------------------------------------------------------------------------
__global__ void init_out_kernel(const float* __restrict__ b4,
                                float* __restrict__ out)
{
    int i = blockIdx.x * blockDim.x + threadIdx.x;
    if (i >= BATCH * 10) return;
    int j = i - (i / 10) * 10;
    out[i] = b4[j];
}

// ---------------------------------------------------------------------------
// Shared GEMM smem layout (both kernels)
// ---------------------------------------------------------------------------
#define SM_A    0
#define SM_B    8192
#define BUF_STRIDE 24576
#define SM_BIAS (2 * BUF_STRIDE)
#define SMEM_SZ (SM_BIAS + 512)

// ---------------------------------------------------------------------------
// L1 GEMM with fp32 A (x) loaded via LDG.128 -> cvt fp16 -> STS (reg double
// buffer); B (W1') fp16 via cp.async. CTA 64x128, 4 warps, K=832 (13 tiles),
// logical A row stride 784 (cols >=784 are zero). relu, fp16 out.
// ---------------------------------------------------------------------------
__global__ void __launch_bounds__(128)
gemm_l1(const float* __restrict__ X,
        const __half* __restrict__ B,
        const float* __restrict__ bias,
        __half* __restrict__ outp)
{
    extern __shared__ __align__(1024) char smem[];
    const uint32_t sb = smem_u32(smem);
    const int tid  = threadIdx.x;
    const int wid  = tid >> 5;
    const int lane = tid & 31;
    const int m0   = blockIdx.y * 64;
    const int N    = 128;
    const int K    = K1P;
    float* bs = (float*)(smem + SM_BIAS);

    bs[tid] = bias[tid];

    // ---- A loader: thread covers half a row (32 cols) = 8 float4 ----
    const int arow  = tid >> 1;            // 0..63
    const int aColB = (tid & 1) * 32;      // col base within tile
    const float* xrow = X + (size_t)(m0 + arow) * 784;
    uint32_t aSts[4];
    #pragma unroll
    for (int j = 0; j < 4; ++j)
        aSts[j] = SWZ128((uint32_t)arow * 128 + (uint32_t)((tid & 1) * 4 + j) * 16);

    // ---- B loader (128 rows x 64 fp16 per tile, SW128) ----
    uint32_t soB[8]; size_t gbOff[8];
    #pragma unroll
    for (int i = 0; i < 8; ++i) {
        const int idx = tid + 128 * i;
        const int row = idx >> 3, ch = idx & 7;
        soB[i]  = SWZ128((uint32_t)row * 128 + ch * 16);
        gbOff[i] = (size_t)row * K + ch * 8;
    }

    // preload tile 0: B via cp.async, A into registers
    #pragma unroll
    for (int i = 0; i < 8; ++i)
        CP_ASYNC16(sb + SM_B + soB[i], B + gbOff[i]);
    CP_COMMIT();

    float4 xa[8];
    #pragma unroll
    for (int q = 0; q < 8; ++q) {
        const int col = aColB + q * 4;
        xa[q] = (col < 784) ? *(const float4*)(xrow + col)
                            : make_float4(0.f, 0.f, 0.f, 0.f);
    }

    const int wm = wid & 1;
    const int wn = wid >> 1;
    const int lrow  = lane & 15;
    const int lhalf = (lane >> 4) * 16;

    float acc[2][8][4];
    #pragma unroll
    for (int mi = 0; mi < 2; ++mi)
        #pragma unroll
        for (int nj = 0; nj < 8; ++nj)
            #pragma unroll
            for (int q = 0; q < 4; ++q) acc[mi][nj][q] = 0.f;

    int buf = 0;
    for (int kt = 0; kt < K; kt += 64) {
        // store A regs (tile kt) into smem buf
        const uint32_t ab = sb + buf * BUF_STRIDE + SM_A;
        #pragma unroll
        for (int j = 0; j < 4; ++j) {
            uint4 v;
            v.x = pack_h2f(xa[2 * j].x,     xa[2 * j].y);
            v.y = pack_h2f(xa[2 * j].z,     xa[2 * j].w);
            v.z = pack_h2f(xa[2 * j + 1].x, xa[2 * j + 1].y);
            v.w = pack_h2f(xa[2 * j + 1].z, xa[2 * j + 1].w);
            *(uint4*)(smem + (buf * BUF_STRIDE + SM_A) + (aSts[j])) = v;
        }
        CP_WAIT0();
        __syncthreads();

        if (kt + 64 < K) {
            const uint32_t nb = sb + (buf ^ 1) * BUF_STRIDE;
            #pragma unroll
            for (int i = 0; i < 8; ++i)
                CP_ASYNC16(nb + SM_B + soB[i], B + gbOff[i] + kt + 64);
            CP_COMMIT();
            #pragma unroll
            for (int q = 0; q < 8; ++q) {
                const int col = kt + 64 + aColB + q * 4;
                xa[q] = (col < 784) ? *(const float4*)(xrow + col)
                                    : make_float4(0.f, 0.f, 0.f, 0.f);
            }
        }

        const uint32_t cb = sb + buf * BUF_STRIDE;
        #pragma unroll
        for (int ks = 0; ks < 4; ++ks) {
            const uint32_t kbyte = ks * 32 + lhalf;
            uint32_t av[2][4];
            #pragma unroll
            for (int mi = 0; mi < 2; ++mi) {
                const uint32_t row = wm * 32 + mi * 16 + lrow;
                LDSM_X4(av[mi], cb + SM_A + SWZ128(row * 128 + kbyte));
            }
            uint32_t bv[4][4];
            #pragma unroll
            for (int g = 0; g < 4; ++g) {
                const uint32_t row = wn * 64 + g * 16 + lrow;
                LDSM_X4(bv[g], cb + SM_B + SWZ128(row * 128 + kbyte));
            }
            #pragma unroll
            for (int mi = 0; mi < 2; ++mi) {
                #pragma unroll
                for (int nj = 0; nj < 8; ++nj) {
                    const int g = nj >> 1, h = nj & 1;
                    MMA_F16(acc[mi][nj], av[mi], bv[g][h], bv[g][h + 2]);
                }
            }
        }
        __syncthreads();
        buf ^= 1;
    }

    // ---- epilogue: bias + relu, fp16 stores ----
    const int qr = lane >> 2;
    const int qc = (lane & 3) * 2;
    #pragma unroll
    for (int mi = 0; mi < 2; ++mi) {
        #pragma unroll
        for (int nj = 0; nj < 8; ++nj) {
            const int col = wn * 64 + nj * 8 + qc;
            const float b0 = bs[col], b1 = bs[col + 1];
            #pragma unroll
            for (int half = 0; half < 2; ++half) {
                const int row = wm * 32 + mi * 16 + qr + half * 8;
                float v0 = fmaxf(acc[mi][nj][half * 2 + 0] + b0, 0.f);
                float v1 = fmaxf(acc[mi][nj][half * 2 + 1] + b1, 0.f);
                *(uint32_t*)(outp + (size_t)(m0 + row) * N + col) =
                    pack_h2f(v0, v1);
            }
        }
    }
}

// ---------------------------------------------------------------------------
// Generic mma.sync fp16 GEMM (fp16 A via cp.async). CTA 64x128, 4 warps.
// HEAD=true: fused fc(256->10) epilogue with atomicAdd into out.
// ---------------------------------------------------------------------------
template <bool RELU, bool HALF_OUT, bool HEAD>
__global__ void __launch_bounds__(128)
gemm_mma(const __half* __restrict__ A,
         const __half* __restrict__ B,
         const float* __restrict__ bias,
         void* __restrict__ outp,
         int N, int K,
         const float* __restrict__ w4p)
{
    extern __shared__ __align__(1024) char smem[];
    const uint32_t sb = smem_u32(smem);
    const int tid  = threadIdx.x;
    const int wid  = tid >> 5;
    const int lane = tid & 31;
    const int m0   = blockIdx.y * 64;
    const int n0   = blockIdx.x * 128;
    float* bs = (float*)(smem + SM_BIAS);

    bs[tid] = bias[n0 + tid];

    uint32_t soA[4]; size_t gaOff[4];
    #pragma unroll
    for (int i = 0; i < 4; ++i) {
        const int idx = tid + 128 * i;
        const int row = idx >> 3, ch = idx & 7;
        soA[i]  = SWZ128((uint32_t)row * 128 + ch * 16);
        gaOff[i] = (size_t)(m0 + row) * K + ch * 8;
    }
    uint32_t soB[8]; size_t gbOff[8];
    #pragma unroll
    for (int i = 0; i < 8; ++i) {
        const int idx = tid + 128 * i;
        const int row = idx >> 3, ch = idx & 7;
        soB[i]  = SWZ128((uint32_t)row * 128 + ch * 16);
        gbOff[i] = (size_t)(n0 + row) * K + ch * 8;
    }

    #pragma unroll
    for (int i = 0; i < 4; ++i)
        CP_ASYNC16(sb + SM_A + soA[i], A + gaOff[i]);
    #pragma unroll
    for (int i = 0; i < 8; ++i)
        CP_ASYNC16(sb + SM_B + soB[i], B + gbOff[i]);
    CP_COMMIT();

    const int wm = wid & 1;
    const int wn = wid >> 1;
    const int lrow  = lane & 15;
    const int lhalf = (lane >> 4) * 16;

    float acc[2][8][4];
    #pragma unroll
    for (int mi = 0; mi < 2; ++mi)
        #pragma unroll
        for (int nj = 0; nj < 8; ++nj)
            #pragma unroll
            for (int q = 0; q < 4; ++q) acc[mi][nj][q] = 0.f;

    int buf = 0;
    for (int kt = 0; kt < K; kt += 64) {
        CP_WAIT0();
        __syncthreads();

        if (kt + 64 < K) {
            const uint32_t nb = sb + (buf ^ 1) * BUF_STRIDE;
            #pragma unroll
            for (int i = 0; i < 4; ++i)
                CP_ASYNC16(nb + SM_A + soA[i], A + gaOff[i] + kt + 64);
            #pragma unroll
            for (int i = 0; i < 8; ++i)
                CP_ASYNC16(nb + SM_B + soB[i], B + gbOff[i] + kt + 64);
            CP_COMMIT();
        }

        const uint32_t cb = sb + buf * BUF_STRIDE;
        #pragma unroll
        for (int ks = 0; ks < 4; ++ks) {
            const uint32_t kbyte = ks * 32 + lhalf;
            uint32_t av[2][4];
            #pragma unroll
            for (int mi = 0; mi < 2; ++mi) {
                const uint32_t row = wm * 32 + mi * 16 + lrow;
                LDSM_X4(av[mi], cb + SM_A + SWZ128(row * 128 + kbyte));
            }
            uint32_t bv[4][4];
            #pragma unroll
            for (int g = 0; g < 4; ++g) {
                const uint32_t row = wn * 64 + g * 16 + lrow;
                LDSM_X4(bv[g], cb + SM_B + SWZ128(row * 128 + kbyte));
            }
            #pragma unroll
            for (int mi = 0; mi < 2; ++mi) {
                #pragma unroll
                for (int nj = 0; nj < 8; ++nj) {
                    const int g = nj >> 1, h = nj & 1;
                    MMA_F16(acc[mi][nj], av[mi], bv[g][h], bv[g][h + 2]);
                }
            }
        }
        __syncthreads();
        buf ^= 1;
    }

    const int qr = lane >> 2;
    const int qc = (lane & 3) * 2;

    if (HEAD) {
        float* stage = (float*)smem;               // 64 x 128 fp32
        float* w4s   = (float*)(smem + 32768);     // 10 x 128 fp32
        #pragma unroll
        for (int i = tid; i < 1280; i += 128) {
            const int j = i >> 7, ci = i & 127;
            w4s[i] = w4p[j * 256 + n0 + ci];
        }
        #pragma unroll
        for (int mi = 0; mi < 2; ++mi) {
            #pragma unroll
            for (int nj = 0; nj < 8; ++nj) {
                const int col = wn * 64 + nj * 8 + qc;
                const float b0 = bs[col], b1 = bs[col + 1];
                #pragma unroll
                for (int half = 0; half < 2; ++half) {
                    const int row = wm * 32 + mi * 16 + qr + half * 8;
                    stage[row * 128 + col]     = fmaxf(acc[mi][nj][half * 2 + 0] + b0, 0.f);
                    stage[row * 128 + col + 1] = fmaxf(acc[mi][nj][half * 2 + 1] + b1, 0.f);
                }
            }
        }
        __syncthreads();

        float w4r[10][4];
        #pragma unroll
        for (int j = 0; j < 10; ++j)
            #pragma unroll
            for (int t = 0; t < 4; ++t)
                w4r[j][t] = w4s[j * 128 + lane + 32 * t];

        float* outF = (float*)outp;
        #pragma unroll 1
        for (int rr = 0; rr < 16; ++rr) {
            const int row = wid * 16 + rr;
            float xv[4];
            #pragma unroll
            for (int t = 0; t < 4; ++t)
                xv[t] = stage[row * 128 + lane + 32 * t];
            float pj[10];
            #pragma unroll
            for (int j = 0; j < 10; ++j) {
                float s = xv[0] * w4r[j][0];
                s = fmaf(xv[1], w4r[j][1], s);
                s = fmaf(xv[2], w4r[j][2], s);
                s = fmaf(xv[3], w4r[j][3], s);
                #pragma unroll
                for (int off = 16; off > 0; off >>= 1)
                    s += __shfl_xor_sync(0xffffffffu, s, off);
                pj[j] = s;
            }
            if (lane == 0) {
                #pragma unroll
                for (int j = 0; j < 10; ++j)
                    atomicAdd(&outF[(size_t)(m0 + row) * 10 + j], pj[j]);
            }
        }
    } else {
        #pragma unroll
        for (int mi = 0; mi < 2; ++mi) {
            #pragma unroll
            for (int nj = 0; nj < 8; ++nj) {
                const int col = wn * 64 + nj * 8 + qc;
                const float b0 = bs[col], b1 = bs[col + 1];
                #pragma unroll
                for (int half = 0; half < 2; ++half) {
                    const int row = wm * 32 + mi * 16 + qr + half * 8;
                    float v0 = acc[mi][nj][half * 2 + 0] + b0;
                    float v1 = acc[mi][nj][half * 2 + 1] + b1;
                    if (RELU) { v0 = fmaxf(v0, 0.f); v1 = fmaxf(v1, 0.f); }
                    const size_t g = (size_t)(m0 + row) * N + n0 + col;
                    if (HALF_OUT) {
                        *(uint32_t*)((__half*)outp + g) = pack_h2f(v0, v1);
                    } else {
                        *(float2*)((float*)outp + g) = make_float2(v0, v1);
                    }
                }
            }
        }
    }
}

// ---------------------------------------------------------------------------
// Launch
// ---------------------------------------------------------------------------
extern "C" void kernel_launch(void* const* d_in, const int* in_sizes, int n_in,
                              void* d_out, int out_size)
{
    const float* x  = (const float*)d_in[0];
    const float* wc = (const float*)d_in[1];
    const float* w1 = (const float*)d_in[2];
    const float* b1 = (const float*)d_in[3];
    const float* w2 = (const float*)d_in[4];
    const float* b2 = (const float*)d_in[5];
    const float* w3 = (const float*)d_in[6];
    const float* b3 = (const float*)d_in[7];
    const float* w4 = (const float*)d_in[8];
    const float* b4 = (const float*)d_in[9];
    float* out = (float*)d_out;

    __half *h1, *h2, *w1c, *w2c, *w3c;
    cudaGetSymbolAddress((void**)&h1,  g_h1);
    cudaGetSymbolAddress((void**)&h2,  g_h2);
    cudaGetSymbolAddress((void**)&w1c, g_w1);
    cudaGetSymbolAddress((void**)&w2c, g_w2);
    cudaGetSymbolAddress((void**)&w3c, g_w3);

    cudaFuncSetAttribute((const void*)gemm_l1,
                         cudaFuncAttributeMaxDynamicSharedMemorySize, SMEM_SZ);
    cudaFuncSetAttribute((const void*)gemm_mma<true, true, false>,
                         cudaFuncAttributeMaxDynamicSharedMemorySize, SMEM_SZ);
    cudaFuncSetAttribute((const void*)gemm_mma<true, false, true>,
                         cudaFuncAttributeMaxDynamicSharedMemorySize, SMEM_SZ);

    // weight prep (tiny)
    wfold_kernel<<<(128 * K1P + 255) / 256, 256>>>(w1, wc, w1c);
    wcast_kernel<<<(512 * 128 + 255) / 256, 256>>>(w2, 512, 128, 128, w2c);
    wcast_kernel<<<(256 * 512 + 255) / 256, 256>>>(w3, 256, 512, 512, w3c);

    // out = b4 broadcast (L3 epilogue atomics accumulate on top)
    init_out_kernel<<<(BATCH * 10 + 255) / 256, 256>>>(b4, out);

    // L1 (conv folded): relu([B,784(x)] x W1'^T) -> h1 (fp16)
    gemm_l1<<<dim3(1, BATCH / 64), 128, SMEM_SZ>>>(x, w1c, b1, h1);
    // L2: [B,128] x [512,128]^T -> relu -> h2 (fp16)
    gemm_mma<true, true, false><<<dim3(4, BATCH / 64), 128, SMEM_SZ>>>(
        h1, w2c, b2, h2, 512, 128, nullptr);
    // L3 + head: relu([B,512] x [256,512]^T) @ w4^T + b4 -> out (atomic)
    gemm_mma<true, false, true><<<dim3(2, BATCH / 64), 128, SMEM_SZ>>>(
        h2, w3c, b3, out, 256, 512, w4);
}